// round 8
// baseline (speedup 1.0000x reference)
#include <cuda_runtime.h>
#include <cuda_bf16.h>
#include <math.h>
#include <stdint.h>

// Problem constants (B=2, T=1024)
#define TTOT   2048
#define EMBED  1024
#define HID    2048
#define NE     8

// K-chunk = 32 bf16. smem row = 32 data + 8 pad = 40 elems (80B), 20-u32 stride.
#define KS 40

// ===================== scratch ==============================================
__device__ __align__(16) int   g_counts[NE];
__device__ __align__(16) int   g_slots[NE * TTOT];
__device__ __align__(16) float g_weights[TTOT * 2];
__device__ __align__(16) float g_tmp[(size_t)TTOT * 2 * EMBED];

__device__ __align__(16) __nv_bfloat16 g_x_hi[(size_t)NE * TTOT * EMBED];
__device__ __align__(16) __nv_bfloat16 g_x_lo[(size_t)NE * TTOT * EMBED];
__device__ __align__(16) __nv_bfloat16 g_wgT_hi[(size_t)NE * HID * EMBED];
__device__ __align__(16) __nv_bfloat16 g_wgT_lo[(size_t)NE * HID * EMBED];
__device__ __align__(16) __nv_bfloat16 g_wuT_hi[(size_t)NE * HID * EMBED];
__device__ __align__(16) __nv_bfloat16 g_wuT_lo[(size_t)NE * HID * EMBED];
__device__ __align__(16) __nv_bfloat16 g_wdT_hi[(size_t)NE * EMBED * HID];
__device__ __align__(16) __nv_bfloat16 g_wdT_lo[(size_t)NE * EMBED * HID];
__device__ __align__(16) __nv_bfloat16 g_act_hi[(size_t)NE * TTOT * HID];
__device__ __align__(16) __nv_bfloat16 g_act_lo[(size_t)NE * TTOT * HID];

// ===================== helpers ==============================================
__device__ __forceinline__ void mma16816(float* d, const uint32_t* a, const uint32_t* b)
{
    asm volatile(
        "mma.sync.aligned.m16n8k16.row.col.f32.bf16.bf16.f32 "
        "{%0,%1,%2,%3}, {%4,%5,%6,%7}, {%8,%9}, {%0,%1,%2,%3};"
        : "+f"(d[0]), "+f"(d[1]), "+f"(d[2]), "+f"(d[3])
        : "r"(a[0]), "r"(a[1]), "r"(a[2]), "r"(a[3]), "r"(b[0]), "r"(b[1]));
}

__device__ __forceinline__ uint32_t pack2bf(float x, float y) {
    __nv_bfloat162 h = __floats2bfloat162_rn(x, y);
    return *reinterpret_cast<uint32_t*>(&h);
}

__device__ __forceinline__ float gelu_tanh(float x) {
    const float c = 0.7978845608028654f;
    float inner = c * (x + 0.044715f * x * x * x);
    return 0.5f * x * (1.f + tanhf(inner));
}

// plain gmem -> smem copy of a rows x 32-bf16 tile (smem row stride KS)
__device__ __forceinline__ void ld_tile(__nv_bfloat16* dst, const __nv_bfloat16* src,
                                        int rows, int stride, int tid)
{
    int total = rows * 4;                 // 4 x 16B per row
    for (int o = tid; o < total; o += 256) {
        int r = o >> 2, ch = o & 3;
        *(float4*)(dst + r * KS + ch * 8) =
            *(const float4*)(src + (size_t)r * stride + ch * 8);
    }
}

// ===================== small kernels ========================================
__global__ void zero_counts_kernel() {
    if (threadIdx.x < NE) g_counts[threadIdx.x] = 0;
}

__global__ __launch_bounds__(256) void route_kernel(
    const float* __restrict__ gate_in, const float* __restrict__ gate_k)
{
    int t = blockIdx.x;
    int warp = threadIdx.x >> 5, lane = threadIdx.x & 31;
    __shared__ float logits[NE];
    const float* gr = gate_in + (size_t)t * EMBED;
    float sum = 0.f;
    for (int j = lane; j < EMBED; j += 32)
        sum += gr[j] * gate_k[j * NE + warp];
    #pragma unroll
    for (int o = 16; o > 0; o >>= 1)
        sum += __shfl_down_sync(0xFFFFFFFFu, sum, o);
    if (lane == 0) logits[warp] = sum;
    __syncthreads();
    if (threadIdx.x == 0) {
        int b0 = 0; float v0 = logits[0];
        #pragma unroll
        for (int e = 1; e < NE; e++)
            if (logits[e] > v0) { v0 = logits[e]; b0 = e; }
        int b1 = -1; float v1 = -3.0e38f;
        #pragma unroll
        for (int e = 0; e < NE; e++) {
            if (e == b0) continue;
            if (logits[e] > v1) { v1 = logits[e]; b1 = e; }
        }
        g_weights[t * 2 + 0] = 1.f / (1.f + expf(-v0));
        g_weights[t * 2 + 1] = 1.f / (1.f + expf(-v1));
        int s0 = atomicAdd(&g_counts[b0], 1);
        g_slots[b0 * TTOT + s0] = t * 2 + 0;
        int s1 = atomicAdd(&g_counts[b1], 1);
        g_slots[b1 * TTOT + s1] = t * 2 + 1;
    }
}

// transpose + fp32 -> bf16 hi/lo split: src [e][K][N] -> dst [e][N][K].
// FIX: destinations are __device__ globals selected IN DEVICE CODE (which):
// passing __device__ symbols as host-side kernel args gives the host shadow
// address (ATS-dereferenceable on GB300 -> silent host-memory corruption).
__global__ __launch_bounds__(256) void tconv_kernel(
    const float* __restrict__ src, int which, int K, int N)
{
    __nv_bfloat16* dhi;
    __nv_bfloat16* dlo;
    if (which == 0)      { dhi = g_wgT_hi; dlo = g_wgT_lo; }
    else if (which == 1) { dhi = g_wuT_hi; dlo = g_wuT_lo; }
    else                 { dhi = g_wdT_hi; dlo = g_wdT_lo; }

    __shared__ float tile[32][33];
    int e = blockIdx.z;
    const float* s = src + (size_t)e * K * N;
    int n = blockIdx.x * 32 + threadIdx.x;
    int k = blockIdx.y * 32 + threadIdx.y;
    #pragma unroll
    for (int i = 0; i < 32; i += 8)
        tile[threadIdx.y + i][threadIdx.x] = s[(size_t)(k + i) * N + n];
    __syncthreads();
    int n2 = blockIdx.x * 32 + threadIdx.y;
    int k2 = blockIdx.y * 32 + threadIdx.x;
    size_t base = (size_t)e * N * K;
    #pragma unroll
    for (int i = 0; i < 32; i += 8) {
        float v = tile[threadIdx.x][threadIdx.y + i];
        __nv_bfloat16 hi = __float2bfloat16(v);
        size_t idx = base + (size_t)(n2 + i) * K + k2;
        dhi[idx] = hi;
        dlo[idx] = __float2bfloat16(v - __bfloat162float(hi));
    }
}

// gather x rows per expert slot, bf16 hi/lo, zero the 128-padding rows
__global__ __launch_bounds__(256) void gather_x_kernel(const float* __restrict__ x)
{
    int gid = blockIdx.x;
    int e = gid >> 11;
    int s = gid & (TTOT - 1);
    int count = g_counts[e];
    int padded = (count + 127) & ~127;
    if (s >= padded) return;
    size_t dst = (size_t)(e * TTOT + s) * EMBED;
    if (s < count) {
        int token = g_slots[e * TTOT + s] >> 1;
        const float* xr = x + (size_t)token * EMBED;
        for (int j = threadIdx.x; j < EMBED; j += 256) {
            float v = xr[j];
            __nv_bfloat16 hi = __float2bfloat16(v);
            g_x_hi[dst + j] = hi;
            g_x_lo[dst + j] = __float2bfloat16(v - __bfloat162float(hi));
        }
    } else {
        __nv_bfloat16 z = __float2bfloat16(0.f);
        for (int j = threadIdx.x; j < EMBED; j += 256) {
            g_x_hi[dst + j] = z;
            g_x_lo[dst + j] = z;
        }
    }
}

// ===================== gate/up MMA kernel (mma.sync bf16) ===================
// CTA: M=128 slots x N=64 cols of HID for BOTH gate and up.
// 8 warps as 2(m) x 4(n). K chunks of 32, single-buffered static smem (40KB).
__global__ __launch_bounds__(256, 1) void gateup_mma_kernel()
{
    __shared__ __align__(16) __nv_bfloat16 sAh[128 * KS];
    __shared__ __align__(16) __nv_bfloat16 sAl[128 * KS];
    __shared__ __align__(16) __nv_bfloat16 sGh[64 * KS];
    __shared__ __align__(16) __nv_bfloat16 sGl[64 * KS];
    __shared__ __align__(16) __nv_bfloat16 sUh[64 * KS];
    __shared__ __align__(16) __nv_bfloat16 sUl[64 * KS];

    int e = blockIdx.z;
    int count = g_counts[e];
    int padded = (count + 127) & ~127;
    int rowBase = blockIdx.y * 128;
    if (rowBase >= padded) return;
    int n0 = blockIdx.x * 64;

    int tid = threadIdx.x, wid = tid >> 5, lane = tid & 31;
    int qr = lane >> 2, qc = lane & 3;
    int warpM = (wid >> 2) * 64;
    int warpN = (wid & 3) * 16;

    const __nv_bfloat16* axh = g_x_hi + (size_t)(e * TTOT + rowBase) * EMBED;
    const __nv_bfloat16* axl = g_x_lo + (size_t)(e * TTOT + rowBase) * EMBED;
    const __nv_bfloat16* bgh = g_wgT_hi + (size_t)(e * HID + n0) * EMBED;
    const __nv_bfloat16* bgl = g_wgT_lo + (size_t)(e * HID + n0) * EMBED;
    const __nv_bfloat16* buh = g_wuT_hi + (size_t)(e * HID + n0) * EMBED;
    const __nv_bfloat16* bul = g_wuT_lo + (size_t)(e * HID + n0) * EMBED;

    float accg[4][2][4] = {}, accu[4][2][4] = {};

    for (int c = 0; c < EMBED / 32; c++) {
        int k0 = c * 32;
        ld_tile(sAh, axh + k0, 128, EMBED, tid);
        ld_tile(sAl, axl + k0, 128, EMBED, tid);
        ld_tile(sGh, bgh + k0, 64, EMBED, tid);
        ld_tile(sGl, bgl + k0, 64, EMBED, tid);
        ld_tile(sUh, buh + k0, 64, EMBED, tid);
        ld_tile(sUl, bul + k0, 64, EMBED, tid);
        __syncthreads();

        const uint32_t* AH = (const uint32_t*)sAh;
        const uint32_t* AL = (const uint32_t*)sAl;
        const uint32_t* GH = (const uint32_t*)sGh;
        const uint32_t* GL = (const uint32_t*)sGl;
        const uint32_t* UH = (const uint32_t*)sUh;
        const uint32_t* UL = (const uint32_t*)sUl;

        #pragma unroll
        for (int ks = 0; ks < 2; ks++) {
            uint32_t ah[4][4], al[4][4];
            #pragma unroll
            for (int mt = 0; mt < 4; mt++) {
                int r = warpM + mt * 16 + qr;
                int o0 = r * 20 + ks * 8 + qc;
                int o1 = (r + 8) * 20 + ks * 8 + qc;
                ah[mt][0] = AH[o0]; ah[mt][1] = AH[o1];
                ah[mt][2] = AH[o0 + 4]; ah[mt][3] = AH[o1 + 4];
                al[mt][0] = AL[o0]; al[mt][1] = AL[o1];
                al[mt][2] = AL[o0 + 4]; al[mt][3] = AL[o1 + 4];
            }
            uint32_t bghf[2][2], bglf[2][2], buhf[2][2], bulf[2][2];
            #pragma unroll
            for (int nt = 0; nt < 2; nt++) {
                int bn = warpN + nt * 8 + qr;
                int o = bn * 20 + ks * 8 + qc;
                bghf[nt][0] = GH[o]; bghf[nt][1] = GH[o + 4];
                bglf[nt][0] = GL[o]; bglf[nt][1] = GL[o + 4];
                buhf[nt][0] = UH[o]; buhf[nt][1] = UH[o + 4];
                bulf[nt][0] = UL[o]; bulf[nt][1] = UL[o + 4];
            }
            #pragma unroll
            for (int mt = 0; mt < 4; mt++)
                #pragma unroll
                for (int nt = 0; nt < 2; nt++) {
                    mma16816(accg[mt][nt], ah[mt], bghf[nt]);
                    mma16816(accg[mt][nt], ah[mt], bglf[nt]);
                    mma16816(accg[mt][nt], al[mt], bghf[nt]);
                    mma16816(accu[mt][nt], ah[mt], buhf[nt]);
                    mma16816(accu[mt][nt], ah[mt], bulf[nt]);
                    mma16816(accu[mt][nt], al[mt], buhf[nt]);
                }
        }
        __syncthreads();
    }

    // epilogue: act = gelu(gate) * up -> bf16 hi/lo
    size_t slot = (size_t)e * TTOT + rowBase;
    #pragma unroll
    for (int mt = 0; mt < 4; mt++)
        #pragma unroll
        for (int nt = 0; nt < 2; nt++) {
            int r0 = warpM + mt * 16 + qr;
            int col = n0 + warpN + nt * 8 + qc * 2;
            float v00 = gelu_tanh(accg[mt][nt][0]) * accu[mt][nt][0];
            float v01 = gelu_tanh(accg[mt][nt][1]) * accu[mt][nt][1];
            float v10 = gelu_tanh(accg[mt][nt][2]) * accu[mt][nt][2];
            float v11 = gelu_tanh(accg[mt][nt][3]) * accu[mt][nt][3];
            float h00 = __bfloat162float(__float2bfloat16(v00));
            float h01 = __bfloat162float(__float2bfloat16(v01));
            float h10 = __bfloat162float(__float2bfloat16(v10));
            float h11 = __bfloat162float(__float2bfloat16(v11));
            size_t i0 = (slot + r0) * HID + col;
            size_t i1 = (slot + r0 + 8) * HID + col;
            *(uint32_t*)&g_act_hi[i0] = pack2bf(h00, h01);
            *(uint32_t*)&g_act_hi[i1] = pack2bf(h10, h11);
            *(uint32_t*)&g_act_lo[i0] = pack2bf(v00 - h00, v01 - h01);
            *(uint32_t*)&g_act_lo[i1] = pack2bf(v10 - h10, v11 - h11);
        }
}

// ===================== down MMA kernel ======================================
// CTA: M=128 slots x N=128 cols of EMBED. warps 2x4 -> warp 64x32.
__global__ __launch_bounds__(256, 1) void down_mma_kernel(const float* __restrict__ scale)
{
    __shared__ __align__(16) __nv_bfloat16 sAh[128 * KS];
    __shared__ __align__(16) __nv_bfloat16 sAl[128 * KS];
    __shared__ __align__(16) __nv_bfloat16 sBh[128 * KS];
    __shared__ __align__(16) __nv_bfloat16 sBl[128 * KS];

    int e = blockIdx.z;
    int count = g_counts[e];
    int padded = (count + 127) & ~127;
    int rowBase = blockIdx.y * 128;
    if (rowBase >= padded) return;
    int n0 = blockIdx.x * 128;

    int tid = threadIdx.x, wid = tid >> 5, lane = tid & 31;
    int qr = lane >> 2, qc = lane & 3;
    int warpM = (wid >> 2) * 64;
    int warpN = (wid & 3) * 32;

    const __nv_bfloat16* ah = g_act_hi + (size_t)(e * TTOT + rowBase) * HID;
    const __nv_bfloat16* al = g_act_lo + (size_t)(e * TTOT + rowBase) * HID;
    const __nv_bfloat16* bh = g_wdT_hi + (size_t)(e * EMBED + n0) * HID;
    const __nv_bfloat16* bl = g_wdT_lo + (size_t)(e * EMBED + n0) * HID;

    float acc[4][4][4] = {};

    for (int c = 0; c < HID / 32; c++) {
        int k0 = c * 32;
        ld_tile(sAh, ah + k0, 128, HID, tid);
        ld_tile(sAl, al + k0, 128, HID, tid);
        ld_tile(sBh, bh + k0, 128, HID, tid);
        ld_tile(sBl, bl + k0, 128, HID, tid);
        __syncthreads();

        const uint32_t* AH = (const uint32_t*)sAh;
        const uint32_t* AL = (const uint32_t*)sAl;
        const uint32_t* BH = (const uint32_t*)sBh;
        const uint32_t* BL = (const uint32_t*)sBl;

        #pragma unroll
        for (int ks = 0; ks < 2; ks++) {
            uint32_t fah[4][4], fal[4][4];
            #pragma unroll
            for (int mt = 0; mt < 4; mt++) {
                int r = warpM + mt * 16 + qr;
                int o0 = r * 20 + ks * 8 + qc;
                int o1 = (r + 8) * 20 + ks * 8 + qc;
                fah[mt][0] = AH[o0]; fah[mt][1] = AH[o1];
                fah[mt][2] = AH[o0 + 4]; fah[mt][3] = AH[o1 + 4];
                fal[mt][0] = AL[o0]; fal[mt][1] = AL[o1];
                fal[mt][2] = AL[o0 + 4]; fal[mt][3] = AL[o1 + 4];
            }
            uint32_t fbh[4][2], fbl[4][2];
            #pragma unroll
            for (int nt = 0; nt < 4; nt++) {
                int bn = warpN + nt * 8 + qr;
                int o = bn * 20 + ks * 8 + qc;
                fbh[nt][0] = BH[o]; fbh[nt][1] = BH[o + 4];
                fbl[nt][0] = BL[o]; fbl[nt][1] = BL[o + 4];
            }
            #pragma unroll
            for (int mt = 0; mt < 4; mt++)
                #pragma unroll
                for (int nt = 0; nt < 4; nt++) {
                    mma16816(acc[mt][nt], fah[mt], fbh[nt]);
                    mma16816(acc[mt][nt], fah[mt], fbl[nt]);
                    mma16816(acc[mt][nt], fal[mt], fbh[nt]);
                }
        }
        __syncthreads();
    }

    float sc = scale[e];
    #pragma unroll
    for (int mt = 0; mt < 4; mt++) {
        int r0 = warpM + mt * 16 + qr;
        int s0 = rowBase + r0, s1 = rowBase + r0 + 8;
        int p0 = (s0 < count) ? g_slots[e * TTOT + s0] : -1;
        int p1 = (s1 < count) ? g_slots[e * TTOT + s1] : -1;
        #pragma unroll
        for (int nt = 0; nt < 4; nt++) {
            int col = n0 + warpN + nt * 8 + qc * 2;
            if (p0 >= 0) {
                float2 v = make_float2(acc[mt][nt][0] * sc, acc[mt][nt][1] * sc);
                *(float2*)&g_tmp[(size_t)p0 * EMBED + col] = v;
            }
            if (p1 >= 0) {
                float2 v = make_float2(acc[mt][nt][2] * sc, acc[mt][nt][3] * sc);
                *(float2*)&g_tmp[(size_t)p1 * EMBED + col] = v;
            }
        }
    }
}

// ===================== combine ==============================================
__global__ __launch_bounds__(256) void combine_kernel(float* __restrict__ out)
{
    int i = blockIdx.x * blockDim.x + threadIdx.x;
    int t = i >> 10;
    int n = i & 1023;
    float w0 = g_weights[t * 2 + 0];
    float w1 = g_weights[t * 2 + 1];
    out[i] = w0 * g_tmp[(size_t)(t * 2 + 0) * EMBED + n]
           + w1 * g_tmp[(size_t)(t * 2 + 1) * EMBED + n];
}

// ===================== host launcher ========================================
extern "C" void kernel_launch(void* const* d_in, const int* in_sizes, int n_in,
                              void* d_out, int out_size)
{
    const float* x     = (const float*)d_in[0];
    const float* gi    = (const float*)d_in[1];
    const float* gk    = (const float*)d_in[2];
    const float* scale = (const float*)d_in[3];
    const float* wg    = (const float*)d_in[4];
    const float* wu    = (const float*)d_in[5];
    const float* wd    = (const float*)d_in[6];
    float* out = (float*)d_out;

    zero_counts_kernel<<<1, 32>>>();
    route_kernel<<<TTOT, 256>>>(gi, gk);
    gather_x_kernel<<<NE * TTOT, 256>>>(x);
    tconv_kernel<<<dim3(HID / 32, EMBED / 32, NE), dim3(32, 8)>>>(wg, 0, EMBED, HID);
    tconv_kernel<<<dim3(HID / 32, EMBED / 32, NE), dim3(32, 8)>>>(wu, 1, EMBED, HID);
    tconv_kernel<<<dim3(EMBED / 32, HID / 32, NE), dim3(32, 8)>>>(wd, 2, HID, EMBED);

    gateup_mma_kernel<<<dim3(HID / 64, TTOT / 128, NE), 256>>>();
    down_mma_kernel<<<dim3(EMBED / 128, TTOT / 128, NE), 256>>>(scale);
    combine_kernel<<<(TTOT * EMBED) / 256, 256>>>(out);
}

// round 9
// speedup vs baseline: 1.9822x; 1.9822x over previous
#include <cuda_runtime.h>
#include <cuda_bf16.h>
#include <math.h>
#include <stdint.h>

// Problem constants (B=2, T=1024)
#define TTOT   2048
#define EMBED  1024
#define HID    2048
#define NE     8

// K-chunk = 32 bf16. smem row = 32 data + 8 pad = 40 elems (80B), 20-u32 stride.
#define KS 40
#define STAGE_E 20480                 // elems per stage (both kernels) = 40960 B
#define SMEM_BYTES (2 * STAGE_E * 2)  // 81920 B double-buffered

// ===================== scratch ==============================================
__device__ __align__(16) int   g_counts[NE];
__device__ __align__(16) int   g_slots[NE * TTOT];
__device__ __align__(16) float g_weights[TTOT * 2];
__device__ __align__(16) float g_tmp[(size_t)TTOT * 2 * EMBED];

__device__ __align__(16) __nv_bfloat16 g_x_hi[(size_t)NE * TTOT * EMBED];
__device__ __align__(16) __nv_bfloat16 g_x_lo[(size_t)NE * TTOT * EMBED];
__device__ __align__(16) __nv_bfloat16 g_wgT_hi[(size_t)NE * HID * EMBED];
__device__ __align__(16) __nv_bfloat16 g_wgT_lo[(size_t)NE * HID * EMBED];
__device__ __align__(16) __nv_bfloat16 g_wuT_hi[(size_t)NE * HID * EMBED];
__device__ __align__(16) __nv_bfloat16 g_wuT_lo[(size_t)NE * HID * EMBED];
__device__ __align__(16) __nv_bfloat16 g_wdT_hi[(size_t)NE * EMBED * HID];
__device__ __align__(16) __nv_bfloat16 g_wdT_lo[(size_t)NE * EMBED * HID];
__device__ __align__(16) __nv_bfloat16 g_act_hi[(size_t)NE * TTOT * HID];
__device__ __align__(16) __nv_bfloat16 g_act_lo[(size_t)NE * TTOT * HID];

// ===================== helpers ==============================================
__device__ __forceinline__ uint32_t smem_u32(const void* p) {
    uint32_t a;
    asm("{ .reg .u64 t; cvta.to.shared.u64 t, %1; cvt.u32.u64 %0, t; }"
        : "=r"(a) : "l"(p));
    return a;
}
#define CP16(dst, src) \
    asm volatile("cp.async.cg.shared.global [%0], [%1], 16;" :: "r"(dst), "l"(src))
#define CP_COMMIT() asm volatile("cp.async.commit_group;" ::: "memory")
#define CP_WAIT1()  asm volatile("cp.async.wait_group 1;" ::: "memory")
#define CP_WAIT0()  asm volatile("cp.async.wait_group 0;" ::: "memory")

__device__ __forceinline__ void mma16816(float* d, const uint32_t* a, const uint32_t* b)
{
    asm volatile(
        "mma.sync.aligned.m16n8k16.row.col.f32.bf16.bf16.f32 "
        "{%0,%1,%2,%3}, {%4,%5,%6,%7}, {%8,%9}, {%0,%1,%2,%3};"
        : "+f"(d[0]), "+f"(d[1]), "+f"(d[2]), "+f"(d[3])
        : "r"(a[0]), "r"(a[1]), "r"(a[2]), "r"(a[3]), "r"(b[0]), "r"(b[1]));
}

__device__ __forceinline__ uint32_t pack2bf(float x, float y) {
    __nv_bfloat162 h = __floats2bfloat162_rn(x, y);
    return *reinterpret_cast<uint32_t*>(&h);
}

__device__ __forceinline__ float gelu_tanh(float x) {
    const float c = 0.7978845608028654f;
    float inner = c * (x + 0.044715f * x * x * x);
    return 0.5f * x * (1.f + tanhf(inner));
}

// async gmem -> smem copy of a rows x 32-bf16 tile (smem row stride KS)
__device__ __forceinline__ void cp_tile(uint32_t dst_sb, const __nv_bfloat16* src,
                                        int rows, int stride, int tid)
{
    int total = rows * 4;                 // 4 x 16B per row
    for (int o = tid; o < total; o += 256) {
        int r = o >> 2, ch = o & 3;
        uint32_t d = dst_sb + (uint32_t)r * (KS * 2) + ch * 16;
        CP16(d, src + (size_t)r * stride + ch * 8);
    }
}

// ===================== small kernels ========================================
__global__ void zero_counts_kernel() {
    if (threadIdx.x < NE) g_counts[threadIdx.x] = 0;
}

__global__ __launch_bounds__(256) void route_kernel(
    const float* __restrict__ gate_in, const float* __restrict__ gate_k)
{
    int t = blockIdx.x;
    int warp = threadIdx.x >> 5, lane = threadIdx.x & 31;
    __shared__ float logits[NE];
    const float* gr = gate_in + (size_t)t * EMBED;
    float sum = 0.f;
    for (int j = lane; j < EMBED; j += 32)
        sum += gr[j] * gate_k[j * NE + warp];
    #pragma unroll
    for (int o = 16; o > 0; o >>= 1)
        sum += __shfl_down_sync(0xFFFFFFFFu, sum, o);
    if (lane == 0) logits[warp] = sum;
    __syncthreads();
    if (threadIdx.x == 0) {
        int b0 = 0; float v0 = logits[0];
        #pragma unroll
        for (int e = 1; e < NE; e++)
            if (logits[e] > v0) { v0 = logits[e]; b0 = e; }
        int b1 = -1; float v1 = -3.0e38f;
        #pragma unroll
        for (int e = 0; e < NE; e++) {
            if (e == b0) continue;
            if (logits[e] > v1) { v1 = logits[e]; b1 = e; }
        }
        g_weights[t * 2 + 0] = 1.f / (1.f + expf(-v0));
        g_weights[t * 2 + 1] = 1.f / (1.f + expf(-v1));
        int s0 = atomicAdd(&g_counts[b0], 1);
        g_slots[b0 * TTOT + s0] = t * 2 + 0;
        int s1 = atomicAdd(&g_counts[b1], 1);
        g_slots[b1 * TTOT + s1] = t * 2 + 1;
    }
}

// transpose + fp32 -> bf16 hi/lo split: src [e][K][N] -> dst [e][N][K].
// Destinations are __device__ globals selected IN DEVICE CODE (which):
// passing __device__ symbols as host-side kernel args gives the host shadow
// address (ATS-dereferenceable on GB300 -> silent host-memory corruption).
__global__ __launch_bounds__(256) void tconv_kernel(
    const float* __restrict__ src, int which, int K, int N)
{
    __nv_bfloat16* dhi;
    __nv_bfloat16* dlo;
    if (which == 0)      { dhi = g_wgT_hi; dlo = g_wgT_lo; }
    else if (which == 1) { dhi = g_wuT_hi; dlo = g_wuT_lo; }
    else                 { dhi = g_wdT_hi; dlo = g_wdT_lo; }

    __shared__ float tile[32][33];
    int e = blockIdx.z;
    const float* s = src + (size_t)e * K * N;
    int n = blockIdx.x * 32 + threadIdx.x;
    int k = blockIdx.y * 32 + threadIdx.y;
    #pragma unroll
    for (int i = 0; i < 32; i += 8)
        tile[threadIdx.y + i][threadIdx.x] = s[(size_t)(k + i) * N + n];
    __syncthreads();
    int n2 = blockIdx.x * 32 + threadIdx.y;
    int k2 = blockIdx.y * 32 + threadIdx.x;
    size_t base = (size_t)e * N * K;
    #pragma unroll
    for (int i = 0; i < 32; i += 8) {
        float v = tile[threadIdx.x][threadIdx.y + i];
        __nv_bfloat16 hi = __float2bfloat16(v);
        size_t idx = base + (size_t)(n2 + i) * K + k2;
        dhi[idx] = hi;
        dlo[idx] = __float2bfloat16(v - __bfloat162float(hi));
    }
}

// gather x rows per expert slot, bf16 hi/lo, zero the 128-padding rows
__global__ __launch_bounds__(256) void gather_x_kernel(const float* __restrict__ x)
{
    int gid = blockIdx.x;
    int e = gid >> 11;
    int s = gid & (TTOT - 1);
    int count = g_counts[e];
    int padded = (count + 127) & ~127;
    if (s >= padded) return;
    size_t dst = (size_t)(e * TTOT + s) * EMBED;
    if (s < count) {
        int token = g_slots[e * TTOT + s] >> 1;
        const float* xr = x + (size_t)token * EMBED;
        for (int j = threadIdx.x; j < EMBED; j += 256) {
            float v = xr[j];
            __nv_bfloat16 hi = __float2bfloat16(v);
            g_x_hi[dst + j] = hi;
            g_x_lo[dst + j] = __float2bfloat16(v - __bfloat162float(hi));
        }
    } else {
        __nv_bfloat16 z = __float2bfloat16(0.f);
        for (int j = threadIdx.x; j < EMBED; j += 256) {
            g_x_hi[dst + j] = z;
            g_x_lo[dst + j] = z;
        }
    }
}

// ===================== gate/up MMA kernel (mma.sync bf16) ===================
// CTA: M=128 slots x N=64 cols of HID for BOTH gate and up.
// 8 warps as 2(m) x 4(n). K chunks of 32, cp.async double-buffered (80KB dyn).
extern __shared__ __nv_bfloat16 dynsm[];

__global__ __launch_bounds__(256, 1) void gateup_mma_kernel()
{
    int e = blockIdx.z;
    int count = g_counts[e];
    int padded = (count + 127) & ~127;
    int rowBase = blockIdx.y * 128;
    if (rowBase >= padded) return;
    int n0 = blockIdx.x * 64;

    int tid = threadIdx.x, wid = tid >> 5, lane = tid & 31;
    int qr = lane >> 2, qc = lane & 3;
    int warpM = (wid >> 2) * 64;
    int warpN = (wid & 3) * 16;

    uint32_t sb = smem_u32(dynsm);
    // stage layout (bf16 elem offsets)
    const int O_AH = 0, O_AL = 5120, O_GH = 10240, O_GL = 12800,
              O_UH = 15360, O_UL = 17920;

    const __nv_bfloat16* axh = g_x_hi + (size_t)(e * TTOT + rowBase) * EMBED;
    const __nv_bfloat16* axl = g_x_lo + (size_t)(e * TTOT + rowBase) * EMBED;
    const __nv_bfloat16* bgh = g_wgT_hi + (size_t)(e * HID + n0) * EMBED;
    const __nv_bfloat16* bgl = g_wgT_lo + (size_t)(e * HID + n0) * EMBED;
    const __nv_bfloat16* buh = g_wuT_hi + (size_t)(e * HID + n0) * EMBED;
    const __nv_bfloat16* bul = g_wuT_lo + (size_t)(e * HID + n0) * EMBED;

    float accg[4][2][4] = {}, accu[4][2][4] = {};

    const int NCH = EMBED / 32;      // 32
    {   // prefetch chunk 0 into stage 0
        cp_tile(sb + O_AH * 2, axh, 128, EMBED, tid);
        cp_tile(sb + O_AL * 2, axl, 128, EMBED, tid);
        cp_tile(sb + O_GH * 2, bgh, 64, EMBED, tid);
        cp_tile(sb + O_GL * 2, bgl, 64, EMBED, tid);
        cp_tile(sb + O_UH * 2, buh, 64, EMBED, tid);
        cp_tile(sb + O_UL * 2, bul, 64, EMBED, tid);
        CP_COMMIT();
    }

    for (int c = 0; c < NCH; c++) {
        if (c + 1 < NCH) {
            uint32_t st = sb + ((c + 1) & 1) * (STAGE_E * 2);
            int k0 = (c + 1) * 32;
            cp_tile(st + O_AH * 2, axh + k0, 128, EMBED, tid);
            cp_tile(st + O_AL * 2, axl + k0, 128, EMBED, tid);
            cp_tile(st + O_GH * 2, bgh + k0, 64, EMBED, tid);
            cp_tile(st + O_GL * 2, bgl + k0, 64, EMBED, tid);
            cp_tile(st + O_UH * 2, buh + k0, 64, EMBED, tid);
            cp_tile(st + O_UL * 2, bul + k0, 64, EMBED, tid);
            CP_COMMIT();
            CP_WAIT1();
        } else {
            CP_WAIT0();
        }
        __syncthreads();

        const uint32_t* S = (const uint32_t*)(dynsm + (c & 1) * STAGE_E);
        const uint32_t* AH = S + O_AH / 2;
        const uint32_t* AL = S + O_AL / 2;
        const uint32_t* GH = S + O_GH / 2;
        const uint32_t* GL = S + O_GL / 2;
        const uint32_t* UH = S + O_UH / 2;
        const uint32_t* UL = S + O_UL / 2;

        #pragma unroll
        for (int ks = 0; ks < 2; ks++) {
            uint32_t ah[4][4], al[4][4];
            #pragma unroll
            for (int mt = 0; mt < 4; mt++) {
                int r = warpM + mt * 16 + qr;
                int o0 = r * 20 + ks * 8 + qc;
                int o1 = (r + 8) * 20 + ks * 8 + qc;
                ah[mt][0] = AH[o0]; ah[mt][1] = AH[o1];
                ah[mt][2] = AH[o0 + 4]; ah[mt][3] = AH[o1 + 4];
                al[mt][0] = AL[o0]; al[mt][1] = AL[o1];
                al[mt][2] = AL[o0 + 4]; al[mt][3] = AL[o1 + 4];
            }
            uint32_t bghf[2][2], bglf[2][2], buhf[2][2], bulf[2][2];
            #pragma unroll
            for (int nt = 0; nt < 2; nt++) {
                int bn = warpN + nt * 8 + qr;
                int o = bn * 20 + ks * 8 + qc;
                bghf[nt][0] = GH[o]; bghf[nt][1] = GH[o + 4];
                bglf[nt][0] = GL[o]; bglf[nt][1] = GL[o + 4];
                buhf[nt][0] = UH[o]; buhf[nt][1] = UH[o + 4];
                bulf[nt][0] = UL[o]; bulf[nt][1] = UL[o + 4];
            }
            #pragma unroll
            for (int mt = 0; mt < 4; mt++)
                #pragma unroll
                for (int nt = 0; nt < 2; nt++) {
                    mma16816(accg[mt][nt], ah[mt], bghf[nt]);
                    mma16816(accg[mt][nt], ah[mt], bglf[nt]);
                    mma16816(accg[mt][nt], al[mt], bghf[nt]);
                    mma16816(accu[mt][nt], ah[mt], buhf[nt]);
                    mma16816(accu[mt][nt], ah[mt], bulf[nt]);
                    mma16816(accu[mt][nt], al[mt], buhf[nt]);
                }
        }
        __syncthreads();
    }

    // epilogue: act = gelu(gate) * up -> bf16 hi/lo
    size_t slot = (size_t)e * TTOT + rowBase;
    #pragma unroll
    for (int mt = 0; mt < 4; mt++)
        #pragma unroll
        for (int nt = 0; nt < 2; nt++) {
            int r0 = warpM + mt * 16 + qr;
            int col = n0 + warpN + nt * 8 + qc * 2;
            float v00 = gelu_tanh(accg[mt][nt][0]) * accu[mt][nt][0];
            float v01 = gelu_tanh(accg[mt][nt][1]) * accu[mt][nt][1];
            float v10 = gelu_tanh(accg[mt][nt][2]) * accu[mt][nt][2];
            float v11 = gelu_tanh(accg[mt][nt][3]) * accu[mt][nt][3];
            float h00 = __bfloat162float(__float2bfloat16(v00));
            float h01 = __bfloat162float(__float2bfloat16(v01));
            float h10 = __bfloat162float(__float2bfloat16(v10));
            float h11 = __bfloat162float(__float2bfloat16(v11));
            size_t i0 = (slot + r0) * HID + col;
            size_t i1 = (slot + r0 + 8) * HID + col;
            *(uint32_t*)&g_act_hi[i0] = pack2bf(h00, h01);
            *(uint32_t*)&g_act_hi[i1] = pack2bf(h10, h11);
            *(uint32_t*)&g_act_lo[i0] = pack2bf(v00 - h00, v01 - h01);
            *(uint32_t*)&g_act_lo[i1] = pack2bf(v10 - h10, v11 - h11);
        }
}

// ===================== down MMA kernel ======================================
// CTA: M=128 slots x N=128 cols of EMBED. warps 2x4 -> warp 64x32.
__global__ __launch_bounds__(256, 1) void down_mma_kernel(const float* __restrict__ scale)
{
    int e = blockIdx.z;
    int count = g_counts[e];
    int padded = (count + 127) & ~127;
    int rowBase = blockIdx.y * 128;
    if (rowBase >= padded) return;
    int n0 = blockIdx.x * 128;

    int tid = threadIdx.x, wid = tid >> 5, lane = tid & 31;
    int qr = lane >> 2, qc = lane & 3;
    int warpM = (wid >> 2) * 64;
    int warpN = (wid & 3) * 32;

    uint32_t sb = smem_u32(dynsm);
    const int O_AH = 0, O_AL = 5120, O_BH = 10240, O_BL = 15360;

    const __nv_bfloat16* ah = g_act_hi + (size_t)(e * TTOT + rowBase) * HID;
    const __nv_bfloat16* al = g_act_lo + (size_t)(e * TTOT + rowBase) * HID;
    const __nv_bfloat16* bh = g_wdT_hi + (size_t)(e * EMBED + n0) * HID;
    const __nv_bfloat16* bl = g_wdT_lo + (size_t)(e * EMBED + n0) * HID;

    float acc[4][4][4] = {};

    const int NCH = HID / 32;       // 64
    {
        cp_tile(sb + O_AH * 2, ah, 128, HID, tid);
        cp_tile(sb + O_AL * 2, al, 128, HID, tid);
        cp_tile(sb + O_BH * 2, bh, 128, HID, tid);
        cp_tile(sb + O_BL * 2, bl, 128, HID, tid);
        CP_COMMIT();
    }

    for (int c = 0; c < NCH; c++) {
        if (c + 1 < NCH) {
            uint32_t st = sb + ((c + 1) & 1) * (STAGE_E * 2);
            int k0 = (c + 1) * 32;
            cp_tile(st + O_AH * 2, ah + k0, 128, HID, tid);
            cp_tile(st + O_AL * 2, al + k0, 128, HID, tid);
            cp_tile(st + O_BH * 2, bh + k0, 128, HID, tid);
            cp_tile(st + O_BL * 2, bl + k0, 128, HID, tid);
            CP_COMMIT();
            CP_WAIT1();
        } else {
            CP_WAIT0();
        }
        __syncthreads();

        const uint32_t* S = (const uint32_t*)(dynsm + (c & 1) * STAGE_E);
        const uint32_t* AH = S + O_AH / 2;
        const uint32_t* AL = S + O_AL / 2;
        const uint32_t* BH = S + O_BH / 2;
        const uint32_t* BL = S + O_BL / 2;

        #pragma unroll
        for (int ks = 0; ks < 2; ks++) {
            uint32_t fah[4][4], fal[4][4];
            #pragma unroll
            for (int mt = 0; mt < 4; mt++) {
                int r = warpM + mt * 16 + qr;
                int o0 = r * 20 + ks * 8 + qc;
                int o1 = (r + 8) * 20 + ks * 8 + qc;
                fah[mt][0] = AH[o0]; fah[mt][1] = AH[o1];
                fah[mt][2] = AH[o0 + 4]; fah[mt][3] = AH[o1 + 4];
                fal[mt][0] = AL[o0]; fal[mt][1] = AL[o1];
                fal[mt][2] = AL[o0 + 4]; fal[mt][3] = AL[o1 + 4];
            }
            uint32_t fbh[4][2], fbl[4][2];
            #pragma unroll
            for (int nt = 0; nt < 4; nt++) {
                int bn = warpN + nt * 8 + qr;
                int o = bn * 20 + ks * 8 + qc;
                fbh[nt][0] = BH[o]; fbh[nt][1] = BH[o + 4];
                fbl[nt][0] = BL[o]; fbl[nt][1] = BL[o + 4];
            }
            #pragma unroll
            for (int mt = 0; mt < 4; mt++)
                #pragma unroll
                for (int nt = 0; nt < 4; nt++) {
                    mma16816(acc[mt][nt], fah[mt], fbh[nt]);
                    mma16816(acc[mt][nt], fah[mt], fbl[nt]);
                    mma16816(acc[mt][nt], fal[mt], fbh[nt]);
                }
        }
        __syncthreads();
    }

    float sc = scale[e];
    #pragma unroll
    for (int mt = 0; mt < 4; mt++) {
        int r0 = warpM + mt * 16 + qr;
        int s0 = rowBase + r0, s1 = rowBase + r0 + 8;
        int p0 = (s0 < count) ? g_slots[e * TTOT + s0] : -1;
        int p1 = (s1 < count) ? g_slots[e * TTOT + s1] : -1;
        #pragma unroll
        for (int nt = 0; nt < 4; nt++) {
            int col = n0 + warpN + nt * 8 + qc * 2;
            if (p0 >= 0) {
                float2 v = make_float2(acc[mt][nt][0] * sc, acc[mt][nt][1] * sc);
                *(float2*)&g_tmp[(size_t)p0 * EMBED + col] = v;
            }
            if (p1 >= 0) {
                float2 v = make_float2(acc[mt][nt][2] * sc, acc[mt][nt][3] * sc);
                *(float2*)&g_tmp[(size_t)p1 * EMBED + col] = v;
            }
        }
    }
}

// ===================== combine ==============================================
__global__ __launch_bounds__(256) void combine_kernel(float* __restrict__ out)
{
    int i = blockIdx.x * blockDim.x + threadIdx.x;
    int t = i >> 10;
    int n = i & 1023;
    float w0 = g_weights[t * 2 + 0];
    float w1 = g_weights[t * 2 + 1];
    out[i] = w0 * g_tmp[(size_t)(t * 2 + 0) * EMBED + n]
           + w1 * g_tmp[(size_t)(t * 2 + 1) * EMBED + n];
}

// ===================== host launcher ========================================
extern "C" void kernel_launch(void* const* d_in, const int* in_sizes, int n_in,
                              void* d_out, int out_size)
{
    const float* x     = (const float*)d_in[0];
    const float* gi    = (const float*)d_in[1];
    const float* gk    = (const float*)d_in[2];
    const float* scale = (const float*)d_in[3];
    const float* wg    = (const float*)d_in[4];
    const float* wu    = (const float*)d_in[5];
    const float* wd    = (const float*)d_in[6];
    float* out = (float*)d_out;

    cudaFuncSetAttribute(gateup_mma_kernel,
                         cudaFuncAttributeMaxDynamicSharedMemorySize, SMEM_BYTES);
    cudaFuncSetAttribute(down_mma_kernel,
                         cudaFuncAttributeMaxDynamicSharedMemorySize, SMEM_BYTES);

    zero_counts_kernel<<<1, 32>>>();
    route_kernel<<<TTOT, 256>>>(gi, gk);
    gather_x_kernel<<<NE * TTOT, 256>>>(x);
    tconv_kernel<<<dim3(HID / 32, EMBED / 32, NE), dim3(32, 8)>>>(wg, 0, EMBED, HID);
    tconv_kernel<<<dim3(HID / 32, EMBED / 32, NE), dim3(32, 8)>>>(wu, 1, EMBED, HID);
    tconv_kernel<<<dim3(EMBED / 32, NE == 8 ? HID / 32 : 0, NE), dim3(32, 8)>>>(wd, 2, HID, EMBED);

    gateup_mma_kernel<<<dim3(HID / 64, TTOT / 128, NE), 256, SMEM_BYTES>>>();
    down_mma_kernel<<<dim3(EMBED / 128, TTOT / 128, NE), 256, SMEM_BYTES>>>(scale);
    combine_kernel<<<(TTOT * EMBED) / 256, 256>>>(out);
}

// round 10
// speedup vs baseline: 2.2588x; 1.1396x over previous
#include <cuda_runtime.h>
#include <cuda_bf16.h>
#include <math.h>
#include <stdint.h>

// Problem constants (B=2, T=1024)
#define TTOT   2048
#define EMBED  1024
#define HID    2048
#define NE     8

// K-chunk = 64 bf16. smem row = 64 data + 8 pad = 72 elems (144B).
#define KS 72
#define STAGE_E 36864                 // elems per stage (both kernels) = 73728 B
#define SMEM_BYTES (2 * STAGE_E * 2)  // 147456 B double-buffered

// ===================== scratch ==============================================
__device__ __align__(16) int   g_counts[NE];
__device__ __align__(16) int   g_slots[NE * TTOT];
__device__ __align__(16) float g_weights[TTOT * 2];
__device__ __align__(16) float g_tmp[(size_t)TTOT * 2 * EMBED];

__device__ __align__(16) __nv_bfloat16 g_x_hi[(size_t)NE * TTOT * EMBED];
__device__ __align__(16) __nv_bfloat16 g_x_lo[(size_t)NE * TTOT * EMBED];
__device__ __align__(16) __nv_bfloat16 g_wgT_hi[(size_t)NE * HID * EMBED];
__device__ __align__(16) __nv_bfloat16 g_wgT_lo[(size_t)NE * HID * EMBED];
__device__ __align__(16) __nv_bfloat16 g_wuT_hi[(size_t)NE * HID * EMBED];
__device__ __align__(16) __nv_bfloat16 g_wuT_lo[(size_t)NE * HID * EMBED];
__device__ __align__(16) __nv_bfloat16 g_wdT_hi[(size_t)NE * EMBED * HID];
__device__ __align__(16) __nv_bfloat16 g_wdT_lo[(size_t)NE * EMBED * HID];
__device__ __align__(16) __nv_bfloat16 g_act_hi[(size_t)NE * TTOT * HID];
__device__ __align__(16) __nv_bfloat16 g_act_lo[(size_t)NE * TTOT * HID];

// ===================== helpers ==============================================
__device__ __forceinline__ uint32_t smem_u32(const void* p) {
    uint32_t a;
    asm("{ .reg .u64 t; cvta.to.shared.u64 t, %1; cvt.u32.u64 %0, t; }"
        : "=r"(a) : "l"(p));
    return a;
}
#define CP16(dst, src) \
    asm volatile("cp.async.cg.shared.global [%0], [%1], 16;" :: "r"(dst), "l"(src))
#define CP_COMMIT() asm volatile("cp.async.commit_group;" ::: "memory")
#define CP_WAIT1()  asm volatile("cp.async.wait_group 1;" ::: "memory")
#define CP_WAIT0()  asm volatile("cp.async.wait_group 0;" ::: "memory")

#define LDSM_X4(r, addr) \
    asm volatile("ldmatrix.sync.aligned.m8n8.x4.shared.b16 {%0,%1,%2,%3}, [%4];" \
        : "=r"((r)[0]), "=r"((r)[1]), "=r"((r)[2]), "=r"((r)[3]) : "r"(addr))

__device__ __forceinline__ void mma16816(float* d, const uint32_t* a, const uint32_t* b)
{
    asm volatile(
        "mma.sync.aligned.m16n8k16.row.col.f32.bf16.bf16.f32 "
        "{%0,%1,%2,%3}, {%4,%5,%6,%7}, {%8,%9}, {%0,%1,%2,%3};"
        : "+f"(d[0]), "+f"(d[1]), "+f"(d[2]), "+f"(d[3])
        : "r"(a[0]), "r"(a[1]), "r"(a[2]), "r"(a[3]), "r"(b[0]), "r"(b[1]));
}

__device__ __forceinline__ uint32_t pack2bf(float x, float y) {
    __nv_bfloat162 h = __floats2bfloat162_rn(x, y);
    return *reinterpret_cast<uint32_t*>(&h);
}

__device__ __forceinline__ float gelu_tanh(float x) {
    const float c = 0.7978845608028654f;
    float inner = c * (x + 0.044715f * x * x * x);
    return 0.5f * x * (1.f + tanhf(inner));
}

// async gmem -> smem copy of a rows x 64-bf16 tile (smem row stride KS)
__device__ __forceinline__ void cp_tile(uint32_t dst_sb, const __nv_bfloat16* src,
                                        int rows, int stride, int tid)
{
    int total = rows * 8;                 // 8 x 16B per row
    for (int o = tid; o < total; o += 256) {
        int r = o >> 3, ch = o & 7;
        uint32_t d = dst_sb + (uint32_t)r * (KS * 2) + ch * 16;
        CP16(d, src + (size_t)r * stride + ch * 8);
    }
}

// ===================== small kernels ========================================
__global__ void zero_counts_kernel() {
    if (threadIdx.x < NE) g_counts[threadIdx.x] = 0;
}

__global__ __launch_bounds__(256) void route_kernel(
    const float* __restrict__ gate_in, const float* __restrict__ gate_k)
{
    int t = blockIdx.x;
    int warp = threadIdx.x >> 5, lane = threadIdx.x & 31;
    __shared__ float logits[NE];
    const float* gr = gate_in + (size_t)t * EMBED;
    float sum = 0.f;
    for (int j = lane; j < EMBED; j += 32)
        sum += gr[j] * gate_k[j * NE + warp];
    #pragma unroll
    for (int o = 16; o > 0; o >>= 1)
        sum += __shfl_down_sync(0xFFFFFFFFu, sum, o);
    if (lane == 0) logits[warp] = sum;
    __syncthreads();
    if (threadIdx.x == 0) {
        int b0 = 0; float v0 = logits[0];
        #pragma unroll
        for (int e = 1; e < NE; e++)
            if (logits[e] > v0) { v0 = logits[e]; b0 = e; }
        int b1 = -1; float v1 = -3.0e38f;
        #pragma unroll
        for (int e = 0; e < NE; e++) {
            if (e == b0) continue;
            if (logits[e] > v1) { v1 = logits[e]; b1 = e; }
        }
        g_weights[t * 2 + 0] = 1.f / (1.f + expf(-v0));
        g_weights[t * 2 + 1] = 1.f / (1.f + expf(-v1));
        int s0 = atomicAdd(&g_counts[b0], 1);
        g_slots[b0 * TTOT + s0] = t * 2 + 0;
        int s1 = atomicAdd(&g_counts[b1], 1);
        g_slots[b1 * TTOT + s1] = t * 2 + 1;
    }
}

// transpose + fp32 -> bf16 hi/lo split: src [e][K][N] -> dst [e][N][K].
// Destinations selected IN DEVICE CODE (ATS host-shadow-pointer hazard).
__global__ __launch_bounds__(256) void tconv_kernel(
    const float* __restrict__ src, int which, int K, int N)
{
    __nv_bfloat16* dhi;
    __nv_bfloat16* dlo;
    if (which == 0)      { dhi = g_wgT_hi; dlo = g_wgT_lo; }
    else if (which == 1) { dhi = g_wuT_hi; dlo = g_wuT_lo; }
    else                 { dhi = g_wdT_hi; dlo = g_wdT_lo; }

    __shared__ float tile[32][33];
    int e = blockIdx.z;
    const float* s = src + (size_t)e * K * N;
    int n = blockIdx.x * 32 + threadIdx.x;
    int k = blockIdx.y * 32 + threadIdx.y;
    #pragma unroll
    for (int i = 0; i < 32; i += 8)
        tile[threadIdx.y + i][threadIdx.x] = s[(size_t)(k + i) * N + n];
    __syncthreads();
    int n2 = blockIdx.x * 32 + threadIdx.y;
    int k2 = blockIdx.y * 32 + threadIdx.x;
    size_t base = (size_t)e * N * K;
    #pragma unroll
    for (int i = 0; i < 32; i += 8) {
        float v = tile[threadIdx.x][threadIdx.y + i];
        __nv_bfloat16 hi = __float2bfloat16(v);
        size_t idx = base + (size_t)(n2 + i) * K + k2;
        dhi[idx] = hi;
        dlo[idx] = __float2bfloat16(v - __bfloat162float(hi));
    }
}

// gather x rows per expert slot, bf16 hi/lo, zero the 128-padding rows
__global__ __launch_bounds__(256) void gather_x_kernel(const float* __restrict__ x)
{
    int gid = blockIdx.x;
    int e = gid >> 11;
    int s = gid & (TTOT - 1);
    int count = g_counts[e];
    int padded = (count + 127) & ~127;
    if (s >= padded) return;
    size_t dst = (size_t)(e * TTOT + s) * EMBED;
    if (s < count) {
        int token = g_slots[e * TTOT + s] >> 1;
        const float* xr = x + (size_t)token * EMBED;
        for (int j = threadIdx.x; j < EMBED; j += 256) {
            float v = xr[j];
            __nv_bfloat16 hi = __float2bfloat16(v);
            g_x_hi[dst + j] = hi;
            g_x_lo[dst + j] = __float2bfloat16(v - __bfloat162float(hi));
        }
    } else {
        __nv_bfloat16 z = __float2bfloat16(0.f);
        for (int j = threadIdx.x; j < EMBED; j += 256) {
            g_x_hi[dst + j] = z;
            g_x_lo[dst + j] = z;
        }
    }
}

// ===================== gate/up MMA kernel (mma.sync bf16 + ldmatrix) ========
// CTA: M=128 slots x N=64 cols of HID for BOTH gate and up.
// 8 warps as 2(m) x 4(n). K chunks of 64, cp.async double-buffered (144KB dyn).
extern __shared__ __nv_bfloat16 dynsm[];

__global__ __launch_bounds__(256, 1) void gateup_mma_kernel()
{
    int e = blockIdx.z;
    int count = g_counts[e];
    int padded = (count + 127) & ~127;
    int rowBase = blockIdx.y * 128;
    if (rowBase >= padded) return;
    int n0 = blockIdx.x * 64;

    int tid = threadIdx.x, wid = tid >> 5, lane = tid & 31;
    int qr = lane >> 2, qc = lane & 3;
    int warpM = (wid >> 2) * 64;
    int warpN = (wid & 3) * 16;

    uint32_t sb = smem_u32(dynsm);
    // stage layout (bf16 elem offsets): A 128x72 x2, B 64x72 x4
    const int O_AH = 0, O_AL = 9216, O_GH = 18432, O_GL = 23040,
              O_UH = 27648, O_UL = 32256;

    // ldmatrix lane addressing (byte offsets within a tile)
    // A x4: tiles = {m0-7,k0}{m8-15,k0}{m0-7,k+8}{m8-15,k+8}
    int rowA = warpM + (lane & 7) + ((lane >> 3) & 1) * 8;
    int kgA  = ((lane >> 4) & 1) * 8;
    uint32_t aoff = (uint32_t)(rowA * KS + kgA) * 2;
    // B x4: tiles = {n0-7,k0}{n0-7,k+8}{n8-15,k0}{n8-15,k+8}
    int rowB = warpN + ((lane >> 4) & 1) * 8 + (lane & 7);
    int kgB  = ((lane >> 3) & 1) * 8;
    uint32_t boff = (uint32_t)(rowB * KS + kgB) * 2;

    const __nv_bfloat16* axh = g_x_hi + (size_t)(e * TTOT + rowBase) * EMBED;
    const __nv_bfloat16* axl = g_x_lo + (size_t)(e * TTOT + rowBase) * EMBED;
    const __nv_bfloat16* bgh = g_wgT_hi + (size_t)(e * HID + n0) * EMBED;
    const __nv_bfloat16* bgl = g_wgT_lo + (size_t)(e * HID + n0) * EMBED;
    const __nv_bfloat16* buh = g_wuT_hi + (size_t)(e * HID + n0) * EMBED;
    const __nv_bfloat16* bul = g_wuT_lo + (size_t)(e * HID + n0) * EMBED;

    float accg[4][2][4] = {}, accu[4][2][4] = {};

    const int NCH = EMBED / 64;      // 16
    {   // prefetch chunk 0 into stage 0
        cp_tile(sb + O_AH * 2, axh, 128, EMBED, tid);
        cp_tile(sb + O_AL * 2, axl, 128, EMBED, tid);
        cp_tile(sb + O_GH * 2, bgh, 64, EMBED, tid);
        cp_tile(sb + O_GL * 2, bgl, 64, EMBED, tid);
        cp_tile(sb + O_UH * 2, buh, 64, EMBED, tid);
        cp_tile(sb + O_UL * 2, bul, 64, EMBED, tid);
        CP_COMMIT();
    }

    for (int c = 0; c < NCH; c++) {
        if (c + 1 < NCH) {
            uint32_t st = sb + ((c + 1) & 1) * (STAGE_E * 2);
            int k0 = (c + 1) * 64;
            cp_tile(st + O_AH * 2, axh + k0, 128, EMBED, tid);
            cp_tile(st + O_AL * 2, axl + k0, 128, EMBED, tid);
            cp_tile(st + O_GH * 2, bgh + k0, 64, EMBED, tid);
            cp_tile(st + O_GL * 2, bgl + k0, 64, EMBED, tid);
            cp_tile(st + O_UH * 2, buh + k0, 64, EMBED, tid);
            cp_tile(st + O_UL * 2, bul + k0, 64, EMBED, tid);
            CP_COMMIT();
            CP_WAIT1();
        } else {
            CP_WAIT0();
        }
        __syncthreads();

        uint32_t sbase = sb + (c & 1) * (STAGE_E * 2);
        uint32_t aAH = sbase + O_AH * 2 + aoff;
        uint32_t aAL = sbase + O_AL * 2 + aoff;
        uint32_t aGH = sbase + O_GH * 2 + boff;
        uint32_t aGL = sbase + O_GL * 2 + boff;
        uint32_t aUH = sbase + O_UH * 2 + boff;
        uint32_t aUL = sbase + O_UL * 2 + boff;

        #pragma unroll
        for (int ks = 0; ks < 4; ks++) {
            uint32_t kb = ks * 32;               // 16 elems = 32 B per k-step
            uint32_t ah[4][4], al[4][4];
            #pragma unroll
            for (int mt = 0; mt < 4; mt++) {
                uint32_t mo = mt * (16 * KS * 2) + kb;
                LDSM_X4(ah[mt], aAH + mo);
                LDSM_X4(al[mt], aAL + mo);
            }
            uint32_t gh4[4], gl4[4], uh4[4], ul4[4];
            LDSM_X4(gh4, aGH + kb);
            LDSM_X4(gl4, aGL + kb);
            LDSM_X4(uh4, aUH + kb);
            LDSM_X4(ul4, aUL + kb);

            #pragma unroll
            for (int mt = 0; mt < 4; mt++)
                #pragma unroll
                for (int nt = 0; nt < 2; nt++) {
                    mma16816(accg[mt][nt], ah[mt], &gh4[nt * 2]);
                    mma16816(accg[mt][nt], ah[mt], &gl4[nt * 2]);
                    mma16816(accg[mt][nt], al[mt], &gh4[nt * 2]);
                    mma16816(accu[mt][nt], ah[mt], &uh4[nt * 2]);
                    mma16816(accu[mt][nt], ah[mt], &ul4[nt * 2]);
                    mma16816(accu[mt][nt], al[mt], &uh4[nt * 2]);
                }
        }
        __syncthreads();
    }

    // epilogue: act = gelu(gate) * up -> bf16 hi/lo
    size_t slot = (size_t)e * TTOT + rowBase;
    #pragma unroll
    for (int mt = 0; mt < 4; mt++)
        #pragma unroll
        for (int nt = 0; nt < 2; nt++) {
            int r0 = warpM + mt * 16 + qr;
            int col = n0 + warpN + nt * 8 + qc * 2;
            float v00 = gelu_tanh(accg[mt][nt][0]) * accu[mt][nt][0];
            float v01 = gelu_tanh(accg[mt][nt][1]) * accu[mt][nt][1];
            float v10 = gelu_tanh(accg[mt][nt][2]) * accu[mt][nt][2];
            float v11 = gelu_tanh(accg[mt][nt][3]) * accu[mt][nt][3];
            float h00 = __bfloat162float(__float2bfloat16(v00));
            float h01 = __bfloat162float(__float2bfloat16(v01));
            float h10 = __bfloat162float(__float2bfloat16(v10));
            float h11 = __bfloat162float(__float2bfloat16(v11));
            size_t i0 = (slot + r0) * HID + col;
            size_t i1 = (slot + r0 + 8) * HID + col;
            *(uint32_t*)&g_act_hi[i0] = pack2bf(h00, h01);
            *(uint32_t*)&g_act_hi[i1] = pack2bf(h10, h11);
            *(uint32_t*)&g_act_lo[i0] = pack2bf(v00 - h00, v01 - h01);
            *(uint32_t*)&g_act_lo[i1] = pack2bf(v10 - h10, v11 - h11);
        }
}

// ===================== down MMA kernel ======================================
// CTA: M=128 slots x N=128 cols of EMBED. warps 2x4 -> warp 64x32.
__global__ __launch_bounds__(256, 1) void down_mma_kernel(const float* __restrict__ scale)
{
    int e = blockIdx.z;
    int count = g_counts[e];
    int padded = (count + 127) & ~127;
    int rowBase = blockIdx.y * 128;
    if (rowBase >= padded) return;
    int n0 = blockIdx.x * 128;

    int tid = threadIdx.x, wid = tid >> 5, lane = tid & 31;
    int qr = lane >> 2, qc = lane & 3;
    int warpM = (wid >> 2) * 64;
    int warpN = (wid & 3) * 32;

    uint32_t sb = smem_u32(dynsm);
    const int O_AH = 0, O_AL = 9216, O_BH = 18432, O_BL = 27648;

    int rowA = warpM + (lane & 7) + ((lane >> 3) & 1) * 8;
    int kgA  = ((lane >> 4) & 1) * 8;
    uint32_t aoff = (uint32_t)(rowA * KS + kgA) * 2;
    int rowB = warpN + ((lane >> 4) & 1) * 8 + (lane & 7);
    int kgB  = ((lane >> 3) & 1) * 8;
    uint32_t boff = (uint32_t)(rowB * KS + kgB) * 2;

    const __nv_bfloat16* ah = g_act_hi + (size_t)(e * TTOT + rowBase) * HID;
    const __nv_bfloat16* al = g_act_lo + (size_t)(e * TTOT + rowBase) * HID;
    const __nv_bfloat16* bh = g_wdT_hi + (size_t)(e * EMBED + n0) * HID;
    const __nv_bfloat16* bl = g_wdT_lo + (size_t)(e * EMBED + n0) * HID;

    float acc[4][4][4] = {};

    const int NCH = HID / 64;       // 32
    {
        cp_tile(sb + O_AH * 2, ah, 128, HID, tid);
        cp_tile(sb + O_AL * 2, al, 128, HID, tid);
        cp_tile(sb + O_BH * 2, bh, 128, HID, tid);
        cp_tile(sb + O_BL * 2, bl, 128, HID, tid);
        CP_COMMIT();
    }

    for (int c = 0; c < NCH; c++) {
        if (c + 1 < NCH) {
            uint32_t st = sb + ((c + 1) & 1) * (STAGE_E * 2);
            int k0 = (c + 1) * 64;
            cp_tile(st + O_AH * 2, ah + k0, 128, HID, tid);
            cp_tile(st + O_AL * 2, al + k0, 128, HID, tid);
            cp_tile(st + O_BH * 2, bh + k0, 128, HID, tid);
            cp_tile(st + O_BL * 2, bl + k0, 128, HID, tid);
            CP_COMMIT();
            CP_WAIT1();
        } else {
            CP_WAIT0();
        }
        __syncthreads();

        uint32_t sbase = sb + (c & 1) * (STAGE_E * 2);
        uint32_t aAH = sbase + O_AH * 2 + aoff;
        uint32_t aAL = sbase + O_AL * 2 + aoff;
        uint32_t aBH = sbase + O_BH * 2 + boff;
        uint32_t aBL = sbase + O_BL * 2 + boff;

        #pragma unroll
        for (int ks = 0; ks < 4; ks++) {
            uint32_t kb = ks * 32;
            uint32_t fah[4][4], fal[4][4];
            #pragma unroll
            for (int mt = 0; mt < 4; mt++) {
                uint32_t mo = mt * (16 * KS * 2) + kb;
                LDSM_X4(fah[mt], aAH + mo);
                LDSM_X4(fal[mt], aAL + mo);
            }
            uint32_t bh8[8], bl8[8];
            LDSM_X4(bh8,     aBH + kb);
            LDSM_X4(bh8 + 4, aBH + (16 * KS * 2) + kb);
            LDSM_X4(bl8,     aBL + kb);
            LDSM_X4(bl8 + 4, aBL + (16 * KS * 2) + kb);

            #pragma unroll
            for (int mt = 0; mt < 4; mt++)
                #pragma unroll
                for (int nt = 0; nt < 4; nt++) {
                    mma16816(acc[mt][nt], fah[mt], &bh8[nt * 2]);
                    mma16816(acc[mt][nt], fah[mt], &bl8[nt * 2]);
                    mma16816(acc[mt][nt], fal[mt], &bh8[nt * 2]);
                }
        }
        __syncthreads();
    }

    float sc = scale[e];
    #pragma unroll
    for (int mt = 0; mt < 4; mt++) {
        int r0 = warpM + mt * 16 + qr;
        int s0 = rowBase + r0, s1 = rowBase + r0 + 8;
        int p0 = (s0 < count) ? g_slots[e * TTOT + s0] : -1;
        int p1 = (s1 < count) ? g_slots[e * TTOT + s1] : -1;
        #pragma unroll
        for (int nt = 0; nt < 4; nt++) {
            int col = n0 + warpN + nt * 8 + qc * 2;
            if (p0 >= 0) {
                float2 v = make_float2(acc[mt][nt][0] * sc, acc[mt][nt][1] * sc);
                *(float2*)&g_tmp[(size_t)p0 * EMBED + col] = v;
            }
            if (p1 >= 0) {
                float2 v = make_float2(acc[mt][nt][2] * sc, acc[mt][nt][3] * sc);
                *(float2*)&g_tmp[(size_t)p1 * EMBED + col] = v;
            }
        }
    }
}

// ===================== combine ==============================================
__global__ __launch_bounds__(256) void combine_kernel(float* __restrict__ out)
{
    int i = blockIdx.x * blockDim.x + threadIdx.x;
    int t = i >> 10;
    int n = i & 1023;
    float w0 = g_weights[t * 2 + 0];
    float w1 = g_weights[t * 2 + 1];
    out[i] = w0 * g_tmp[(size_t)(t * 2 + 0) * EMBED + n]
           + w1 * g_tmp[(size_t)(t * 2 + 1) * EMBED + n];
}

// ===================== host launcher ========================================
extern "C" void kernel_launch(void* const* d_in, const int* in_sizes, int n_in,
                              void* d_out, int out_size)
{
    const float* x     = (const float*)d_in[0];
    const float* gi    = (const float*)d_in[1];
    const float* gk    = (const float*)d_in[2];
    const float* scale = (const float*)d_in[3];
    const float* wg    = (const float*)d_in[4];
    const float* wu    = (const float*)d_in[5];
    const float* wd    = (const float*)d_in[6];
    float* out = (float*)d_out;

    cudaFuncSetAttribute(gateup_mma_kernel,
                         cudaFuncAttributeMaxDynamicSharedMemorySize, SMEM_BYTES);
    cudaFuncSetAttribute(down_mma_kernel,
                         cudaFuncAttributeMaxDynamicSharedMemorySize, SMEM_BYTES);

    zero_counts_kernel<<<1, 32>>>();
    route_kernel<<<TTOT, 256>>>(gi, gk);
    gather_x_kernel<<<NE * TTOT, 256>>>(x);
    tconv_kernel<<<dim3(HID / 32, EMBED / 32, NE), dim3(32, 8)>>>(wg, 0, EMBED, HID);
    tconv_kernel<<<dim3(HID / 32, EMBED / 32, NE), dim3(32, 8)>>>(wu, 1, EMBED, HID);
    tconv_kernel<<<dim3(EMBED / 32, HID / 32, NE), dim3(32, 8)>>>(wd, 2, HID, EMBED);

    gateup_mma_kernel<<<dim3(HID / 64, TTOT / 128, NE), 256, SMEM_BYTES>>>();
    down_mma_kernel<<<dim3(EMBED / 128, TTOT / 128, NE), 256, SMEM_BYTES>>>(scale);
    combine_kernel<<<(TTOT * EMBED) / 256, 256>>>(out);
}

// round 11
// speedup vs baseline: 4.2565x; 1.8844x over previous
#include <cuda_runtime.h>
#include <cuda_fp16.h>
#include <math.h>
#include <stdint.h>

// Problem constants (B=2, T=1024)
#define TTOT   2048
#define EMBED  1024
#define HID    2048
#define NE     8

// K-chunk = 64 fp16. smem row = 64 data + 8 pad = 72 elems (144B).
#define KS 72
#define STAGE_E 18432                 // elems per stage (both kernels) = 36864 B
#define SMEM_BYTES (2 * STAGE_E * 2)  // 73728 B double-buffered

// ===================== scratch ==============================================
__device__ __align__(16) int   g_counts[NE];
__device__ __align__(16) int   g_slots[NE * TTOT];
__device__ __align__(16) float g_weights[TTOT * 2];
__device__ __align__(16) float g_tmp[(size_t)TTOT * 2 * EMBED];

__device__ __align__(16) __half g_x16[(size_t)NE * TTOT * EMBED];
__device__ __align__(16) __half g_wgT[(size_t)NE * HID * EMBED];
__device__ __align__(16) __half g_wuT[(size_t)NE * HID * EMBED];
__device__ __align__(16) __half g_wdT[(size_t)NE * EMBED * HID];
__device__ __align__(16) __half g_act[(size_t)NE * TTOT * HID];

// ===================== helpers ==============================================
__device__ __forceinline__ uint32_t smem_u32(const void* p) {
    uint32_t a;
    asm("{ .reg .u64 t; cvta.to.shared.u64 t, %1; cvt.u32.u64 %0, t; }"
        : "=r"(a) : "l"(p));
    return a;
}
#define CP16(dst, src) \
    asm volatile("cp.async.cg.shared.global [%0], [%1], 16;" :: "r"(dst), "l"(src))
#define CP_COMMIT() asm volatile("cp.async.commit_group;" ::: "memory")
#define CP_WAIT1()  asm volatile("cp.async.wait_group 1;" ::: "memory")
#define CP_WAIT0()  asm volatile("cp.async.wait_group 0;" ::: "memory")

#define LDSM_X4(r, addr) \
    asm volatile("ldmatrix.sync.aligned.m8n8.x4.shared.b16 {%0,%1,%2,%3}, [%4];" \
        : "=r"((r)[0]), "=r"((r)[1]), "=r"((r)[2]), "=r"((r)[3]) : "r"(addr))

__device__ __forceinline__ void mma16816(float* d, const uint32_t* a, const uint32_t* b)
{
    asm volatile(
        "mma.sync.aligned.m16n8k16.row.col.f32.f16.f16.f32 "
        "{%0,%1,%2,%3}, {%4,%5,%6,%7}, {%8,%9}, {%0,%1,%2,%3};"
        : "+f"(d[0]), "+f"(d[1]), "+f"(d[2]), "+f"(d[3])
        : "r"(a[0]), "r"(a[1]), "r"(a[2]), "r"(a[3]), "r"(b[0]), "r"(b[1]));
}

__device__ __forceinline__ uint32_t pack2h(float x, float y) {
    __half2 h = __floats2half2_rn(x, y);
    return *reinterpret_cast<uint32_t*>(&h);
}

__device__ __forceinline__ float gelu_tanh(float x) {
    const float c = 0.7978845608028654f;
    float inner = c * (x + 0.044715f * x * x * x);
    return 0.5f * x * (1.f + tanhf(inner));
}

// async gmem -> smem copy of a rows x 64-fp16 tile (smem row stride KS)
__device__ __forceinline__ void cp_tile(uint32_t dst_sb, const __half* src,
                                        int rows, int stride, int tid)
{
    int total = rows * 8;                 // 8 x 16B per row
    for (int o = tid; o < total; o += 256) {
        int r = o >> 3, ch = o & 7;
        uint32_t d = dst_sb + (uint32_t)r * (KS * 2) + ch * 16;
        CP16(d, src + (size_t)r * stride + ch * 8);
    }
}

// ===================== small kernels ========================================
__global__ void zero_counts_kernel() {
    if (threadIdx.x < NE) g_counts[threadIdx.x] = 0;
}

__global__ __launch_bounds__(256) void route_kernel(
    const float* __restrict__ gate_in, const float* __restrict__ gate_k)
{
    int t = blockIdx.x;
    int warp = threadIdx.x >> 5, lane = threadIdx.x & 31;
    __shared__ float logits[NE];
    const float* gr = gate_in + (size_t)t * EMBED;
    float sum = 0.f;
    for (int j = lane; j < EMBED; j += 32)
        sum += gr[j] * gate_k[j * NE + warp];
    #pragma unroll
    for (int o = 16; o > 0; o >>= 1)
        sum += __shfl_down_sync(0xFFFFFFFFu, sum, o);
    if (lane == 0) logits[warp] = sum;
    __syncthreads();
    if (threadIdx.x == 0) {
        int b0 = 0; float v0 = logits[0];
        #pragma unroll
        for (int e = 1; e < NE; e++)
            if (logits[e] > v0) { v0 = logits[e]; b0 = e; }
        int b1 = -1; float v1 = -3.0e38f;
        #pragma unroll
        for (int e = 0; e < NE; e++) {
            if (e == b0) continue;
            if (logits[e] > v1) { v1 = logits[e]; b1 = e; }
        }
        g_weights[t * 2 + 0] = 1.f / (1.f + expf(-v0));
        g_weights[t * 2 + 1] = 1.f / (1.f + expf(-v1));
        int s0 = atomicAdd(&g_counts[b0], 1);
        g_slots[b0 * TTOT + s0] = t * 2 + 0;
        int s1 = atomicAdd(&g_counts[b1], 1);
        g_slots[b1 * TTOT + s1] = t * 2 + 1;
    }
}

// transpose + fp32 -> fp16: src [e][K][N] -> dst [e][N][K].
// Destination selected IN DEVICE CODE (ATS host-shadow-pointer hazard).
__global__ __launch_bounds__(256) void tconv_kernel(
    const float* __restrict__ src, int which, int K, int N)
{
    __half* dst;
    if (which == 0)      dst = g_wgT;
    else if (which == 1) dst = g_wuT;
    else                 dst = g_wdT;

    __shared__ float tile[32][33];
    int e = blockIdx.z;
    const float* s = src + (size_t)e * K * N;
    int n = blockIdx.x * 32 + threadIdx.x;
    int k = blockIdx.y * 32 + threadIdx.y;
    #pragma unroll
    for (int i = 0; i < 32; i += 8)
        tile[threadIdx.y + i][threadIdx.x] = s[(size_t)(k + i) * N + n];
    __syncthreads();
    int n2 = blockIdx.x * 32 + threadIdx.y;
    int k2 = blockIdx.y * 32 + threadIdx.x;
    size_t base = (size_t)e * N * K;
    #pragma unroll
    for (int i = 0; i < 32; i += 8) {
        float v = tile[threadIdx.x][threadIdx.y + i];
        dst[base + (size_t)(n2 + i) * K + k2] = __float2half_rn(v);
    }
}

// gather x rows per expert slot -> fp16, zero the 128-padding rows
__global__ __launch_bounds__(256) void gather_x_kernel(const float* __restrict__ x)
{
    int gid = blockIdx.x;
    int e = gid >> 11;
    int s = gid & (TTOT - 1);
    int count = g_counts[e];
    int padded = (count + 127) & ~127;
    if (s >= padded) return;
    size_t dst = (size_t)(e * TTOT + s) * EMBED;
    if (s < count) {
        int token = g_slots[e * TTOT + s] >> 1;
        const float* xr = x + (size_t)token * EMBED;
        for (int j = threadIdx.x; j < EMBED; j += 256)
            g_x16[dst + j] = __float2half_rn(xr[j]);
    } else {
        __half z = __float2half(0.f);
        for (int j = threadIdx.x; j < EMBED; j += 256)
            g_x16[dst + j] = z;
    }
}

// ===================== gate/up MMA kernel (mma.sync fp16 + ldmatrix) ========
// CTA: M=128 slots x N=64 cols of HID for BOTH gate and up.
// 8 warps as 2(m) x 4(n). K chunks of 64, cp.async double-buffered (72KB dyn).
extern __shared__ __half dynsm[];

__global__ __launch_bounds__(256, 1) void gateup_mma_kernel()
{
    int e = blockIdx.z;
    int count = g_counts[e];
    int padded = (count + 127) & ~127;
    int rowBase = blockIdx.y * 128;
    if (rowBase >= padded) return;
    int n0 = blockIdx.x * 64;

    int tid = threadIdx.x, wid = tid >> 5, lane = tid & 31;
    int qr = lane >> 2, qc = lane & 3;
    int warpM = (wid >> 2) * 64;
    int warpN = (wid & 3) * 16;

    uint32_t sb = smem_u32(dynsm);
    // stage layout (fp16 elem offsets): A 128x72, G 64x72, U 64x72
    const int O_A = 0, O_G = 9216, O_U = 13824;

    // ldmatrix lane addressing (byte offsets within a tile)
    int rowA = warpM + (lane & 7) + ((lane >> 3) & 1) * 8;
    int kgA  = ((lane >> 4) & 1) * 8;
    uint32_t aoff = (uint32_t)(rowA * KS + kgA) * 2;
    int rowB = warpN + ((lane >> 4) & 1) * 8 + (lane & 7);
    int kgB  = ((lane >> 3) & 1) * 8;
    uint32_t boff = (uint32_t)(rowB * KS + kgB) * 2;

    const __half* ax = g_x16 + (size_t)(e * TTOT + rowBase) * EMBED;
    const __half* bg = g_wgT + (size_t)(e * HID + n0) * EMBED;
    const __half* bu = g_wuT + (size_t)(e * HID + n0) * EMBED;

    float accg[4][2][4] = {}, accu[4][2][4] = {};

    const int NCH = EMBED / 64;      // 16
    {   // prefetch chunk 0 into stage 0
        cp_tile(sb + O_A * 2, ax, 128, EMBED, tid);
        cp_tile(sb + O_G * 2, bg, 64, EMBED, tid);
        cp_tile(sb + O_U * 2, bu, 64, EMBED, tid);
        CP_COMMIT();
    }

    for (int c = 0; c < NCH; c++) {
        if (c + 1 < NCH) {
            uint32_t st = sb + ((c + 1) & 1) * (STAGE_E * 2);
            int k0 = (c + 1) * 64;
            cp_tile(st + O_A * 2, ax + k0, 128, EMBED, tid);
            cp_tile(st + O_G * 2, bg + k0, 64, EMBED, tid);
            cp_tile(st + O_U * 2, bu + k0, 64, EMBED, tid);
            CP_COMMIT();
            CP_WAIT1();
        } else {
            CP_WAIT0();
        }
        __syncthreads();

        uint32_t sbase = sb + (c & 1) * (STAGE_E * 2);
        uint32_t aA = sbase + O_A * 2 + aoff;
        uint32_t aG = sbase + O_G * 2 + boff;
        uint32_t aU = sbase + O_U * 2 + boff;

        #pragma unroll
        for (int ks = 0; ks < 4; ks++) {
            uint32_t kb = ks * 32;               // 16 elems = 32 B per k-step
            uint32_t a4[4][4];
            #pragma unroll
            for (int mt = 0; mt < 4; mt++)
                LDSM_X4(a4[mt], aA + mt * (16 * KS * 2) + kb);
            uint32_t g4[4], u4[4];
            LDSM_X4(g4, aG + kb);
            LDSM_X4(u4, aU + kb);

            #pragma unroll
            for (int mt = 0; mt < 4; mt++)
                #pragma unroll
                for (int nt = 0; nt < 2; nt++) {
                    mma16816(accg[mt][nt], a4[mt], &g4[nt * 2]);
                    mma16816(accu[mt][nt], a4[mt], &u4[nt * 2]);
                }
        }
        __syncthreads();
    }

    // epilogue: act = gelu(gate) * up -> fp16
    size_t slot = (size_t)e * TTOT + rowBase;
    #pragma unroll
    for (int mt = 0; mt < 4; mt++)
        #pragma unroll
        for (int nt = 0; nt < 2; nt++) {
            int r0 = warpM + mt * 16 + qr;
            int col = n0 + warpN + nt * 8 + qc * 2;
            float v00 = gelu_tanh(accg[mt][nt][0]) * accu[mt][nt][0];
            float v01 = gelu_tanh(accg[mt][nt][1]) * accu[mt][nt][1];
            float v10 = gelu_tanh(accg[mt][nt][2]) * accu[mt][nt][2];
            float v11 = gelu_tanh(accg[mt][nt][3]) * accu[mt][nt][3];
            *(uint32_t*)&g_act[(slot + r0) * HID + col]     = pack2h(v00, v01);
            *(uint32_t*)&g_act[(slot + r0 + 8) * HID + col] = pack2h(v10, v11);
        }
}

// ===================== down MMA kernel ======================================
// CTA: M=128 slots x N=128 cols of EMBED. warps 2x4 -> warp 64x32.
__global__ __launch_bounds__(256, 1) void down_mma_kernel(const float* __restrict__ scale)
{
    int e = blockIdx.z;
    int count = g_counts[e];
    int padded = (count + 127) & ~127;
    int rowBase = blockIdx.y * 128;
    if (rowBase >= padded) return;
    int n0 = blockIdx.x * 128;

    int tid = threadIdx.x, wid = tid >> 5, lane = tid & 31;
    int qr = lane >> 2, qc = lane & 3;
    int warpM = (wid >> 2) * 64;
    int warpN = (wid & 3) * 32;

    uint32_t sb = smem_u32(dynsm);
    const int O_A = 0, O_B = 9216;   // A 128x72, B 128x72

    int rowA = warpM + (lane & 7) + ((lane >> 3) & 1) * 8;
    int kgA  = ((lane >> 4) & 1) * 8;
    uint32_t aoff = (uint32_t)(rowA * KS + kgA) * 2;
    int rowB = warpN + ((lane >> 4) & 1) * 8 + (lane & 7);
    int kgB  = ((lane >> 3) & 1) * 8;
    uint32_t boff = (uint32_t)(rowB * KS + kgB) * 2;

    const __half* aa = g_act + (size_t)(e * TTOT + rowBase) * HID;
    const __half* bb = g_wdT + (size_t)(e * EMBED + n0) * HID;

    float acc[4][4][4] = {};

    const int NCH = HID / 64;       // 32
    {
        cp_tile(sb + O_A * 2, aa, 128, HID, tid);
        cp_tile(sb + O_B * 2, bb, 128, HID, tid);
        CP_COMMIT();
    }

    for (int c = 0; c < NCH; c++) {
        if (c + 1 < NCH) {
            uint32_t st = sb + ((c + 1) & 1) * (STAGE_E * 2);
            int k0 = (c + 1) * 64;
            cp_tile(st + O_A * 2, aa + k0, 128, HID, tid);
            cp_tile(st + O_B * 2, bb + k0, 128, HID, tid);
            CP_COMMIT();
            CP_WAIT1();
        } else {
            CP_WAIT0();
        }
        __syncthreads();

        uint32_t sbase = sb + (c & 1) * (STAGE_E * 2);
        uint32_t aA = sbase + O_A * 2 + aoff;
        uint32_t aB = sbase + O_B * 2 + boff;

        #pragma unroll
        for (int ks = 0; ks < 4; ks++) {
            uint32_t kb = ks * 32;
            uint32_t a4[4][4];
            #pragma unroll
            for (int mt = 0; mt < 4; mt++)
                LDSM_X4(a4[mt], aA + mt * (16 * KS * 2) + kb);
            uint32_t b8[8];
            LDSM_X4(b8,     aB + kb);
            LDSM_X4(b8 + 4, aB + (16 * KS * 2) + kb);

            #pragma unroll
            for (int mt = 0; mt < 4; mt++)
                #pragma unroll
                for (int nt = 0; nt < 4; nt++)
                    mma16816(acc[mt][nt], a4[mt], &b8[nt * 2]);
        }
        __syncthreads();
    }

    float sc = scale[e];
    #pragma unroll
    for (int mt = 0; mt < 4; mt++) {
        int r0 = warpM + mt * 16 + qr;
        int s0 = rowBase + r0, s1 = rowBase + r0 + 8;
        int p0 = (s0 < count) ? g_slots[e * TTOT + s0] : -1;
        int p1 = (s1 < count) ? g_slots[e * TTOT + s1] : -1;
        #pragma unroll
        for (int nt = 0; nt < 4; nt++) {
            int col = n0 + warpN + nt * 8 + qc * 2;
            if (p0 >= 0) {
                float2 v = make_float2(acc[mt][nt][0] * sc, acc[mt][nt][1] * sc);
                *(float2*)&g_tmp[(size_t)p0 * EMBED + col] = v;
            }
            if (p1 >= 0) {
                float2 v = make_float2(acc[mt][nt][2] * sc, acc[mt][nt][3] * sc);
                *(float2*)&g_tmp[(size_t)p1 * EMBED + col] = v;
            }
        }
    }
}

// ===================== combine ==============================================
__global__ __launch_bounds__(256) void combine_kernel(float* __restrict__ out)
{
    int i = blockIdx.x * blockDim.x + threadIdx.x;
    int t = i >> 10;
    int n = i & 1023;
    float w0 = g_weights[t * 2 + 0];
    float w1 = g_weights[t * 2 + 1];
    out[i] = w0 * g_tmp[(size_t)(t * 2 + 0) * EMBED + n]
           + w1 * g_tmp[(size_t)(t * 2 + 1) * EMBED + n];
}

// ===================== host launcher ========================================
extern "C" void kernel_launch(void* const* d_in, const int* in_sizes, int n_in,
                              void* d_out, int out_size)
{
    const float* x     = (const float*)d_in[0];
    const float* gi    = (const float*)d_in[1];
    const float* gk    = (const float*)d_in[2];
    const float* scale = (const float*)d_in[3];
    const float* wg    = (const float*)d_in[4];
    const float* wu    = (const float*)d_in[5];
    const float* wd    = (const float*)d_in[6];
    float* out = (float*)d_out;

    cudaFuncSetAttribute(gateup_mma_kernel,
                         cudaFuncAttributeMaxDynamicSharedMemorySize, SMEM_BYTES);
    cudaFuncSetAttribute(down_mma_kernel,
                         cudaFuncAttributeMaxDynamicSharedMemorySize, SMEM_BYTES);

    zero_counts_kernel<<<1, 32>>>();
    route_kernel<<<TTOT, 256>>>(gi, gk);
    gather_x_kernel<<<NE * TTOT, 256>>>(x);
    tconv_kernel<<<dim3(HID / 32, EMBED / 32, NE), dim3(32, 8)>>>(wg, 0, EMBED, HID);
    tconv_kernel<<<dim3(HID / 32, EMBED / 32, NE), dim3(32, 8)>>>(wu, 1, EMBED, HID);
    tconv_kernel<<<dim3(EMBED / 32, HID / 32, NE), dim3(32, 8)>>>(wd, 2, HID, EMBED);

    gateup_mma_kernel<<<dim3(HID / 64, TTOT / 128, NE), 256, SMEM_BYTES>>>();
    down_mma_kernel<<<dim3(EMBED / 128, TTOT / 128, NE), 256, SMEM_BYTES>>>(scale);
    combine_kernel<<<(TTOT * EMBED) / 256, 256>>>(out);
}

// round 12
// speedup vs baseline: 4.9800x; 1.1700x over previous
#include <cuda_runtime.h>
#include <cuda_fp16.h>
#include <math.h>
#include <stdint.h>

// Problem constants (B=2, T=1024)
#define TTOT   2048
#define EMBED  1024
#define HID    2048
#define NE     8

// K-chunk = 64 fp16. smem row = 64 data + 8 pad = 72 elems (144B).
#define KS 72
#define STAGE_E 18432                 // elems per stage (both kernels) = 36864 B
#define SMEM_BYTES (2 * STAGE_E * 2)  // 73728 B double-buffered

// ===================== scratch ==============================================
__device__ __align__(16) int   g_counts[NE];
__device__ __align__(16) int   g_slots[NE * TTOT];
__device__ __align__(16) float g_weights[TTOT * 2];
__device__ __align__(16) float g_tmp[(size_t)TTOT * 2 * EMBED];

__device__ __align__(16) __half g_x16[(size_t)NE * TTOT * EMBED];
__device__ __align__(16) __half g_wgT[(size_t)NE * HID * EMBED];
__device__ __align__(16) __half g_wuT[(size_t)NE * HID * EMBED];
__device__ __align__(16) __half g_wdT[(size_t)NE * EMBED * HID];
__device__ __align__(16) __half g_act[(size_t)NE * TTOT * HID];

// ===================== helpers ==============================================
__device__ __forceinline__ uint32_t smem_u32(const void* p) {
    uint32_t a;
    asm("{ .reg .u64 t; cvta.to.shared.u64 t, %1; cvt.u32.u64 %0, t; }"
        : "=r"(a) : "l"(p));
    return a;
}
#define CP16(dst, src) \
    asm volatile("cp.async.cg.shared.global [%0], [%1], 16;" :: "r"(dst), "l"(src))
#define CP_COMMIT() asm volatile("cp.async.commit_group;" ::: "memory")
#define CP_WAIT1()  asm volatile("cp.async.wait_group 1;" ::: "memory")
#define CP_WAIT0()  asm volatile("cp.async.wait_group 0;" ::: "memory")

#define LDSM_X4(r, addr) \
    asm volatile("ldmatrix.sync.aligned.m8n8.x4.shared.b16 {%0,%1,%2,%3}, [%4];" \
        : "=r"((r)[0]), "=r"((r)[1]), "=r"((r)[2]), "=r"((r)[3]) : "r"(addr))

__device__ __forceinline__ void mma16816(float* d, const uint32_t* a, const uint32_t* b)
{
    asm volatile(
        "mma.sync.aligned.m16n8k16.row.col.f32.f16.f16.f32 "
        "{%0,%1,%2,%3}, {%4,%5,%6,%7}, {%8,%9}, {%0,%1,%2,%3};"
        : "+f"(d[0]), "+f"(d[1]), "+f"(d[2]), "+f"(d[3])
        : "r"(a[0]), "r"(a[1]), "r"(a[2]), "r"(a[3]), "r"(b[0]), "r"(b[1]));
}

__device__ __forceinline__ uint32_t pack2h(float x, float y) {
    __half2 h = __floats2half2_rn(x, y);
    return *reinterpret_cast<uint32_t*>(&h);
}

__device__ __forceinline__ float gelu_tanh(float x) {
    const float c = 0.7978845608028654f;
    float inner = c * (x + 0.044715f * x * x * x);
    return 0.5f * x * (1.f + tanhf(inner));
}

// async gmem -> smem copy of a rows x 64-fp16 tile (smem row stride KS)
__device__ __forceinline__ void cp_tile(uint32_t dst_sb, const __half* src,
                                        int rows, int stride, int tid)
{
    int total = rows * 8;                 // 8 x 16B per row
    for (int o = tid; o < total; o += 256) {
        int r = o >> 3, ch = o & 7;
        uint32_t d = dst_sb + (uint32_t)r * (KS * 2) + ch * 16;
        CP16(d, src + (size_t)r * stride + ch * 8);
    }
}

// ===================== small kernels ========================================
__global__ void zero_counts_kernel() {
    if (threadIdx.x < NE) g_counts[threadIdx.x] = 0;
}

__global__ __launch_bounds__(256) void route_kernel(
    const float* __restrict__ gate_in, const float* __restrict__ gate_k)
{
    int t = blockIdx.x;
    int warp = threadIdx.x >> 5, lane = threadIdx.x & 31;
    __shared__ float logits[NE];
    const float* gr = gate_in + (size_t)t * EMBED;
    float sum = 0.f;
    for (int j = lane; j < EMBED; j += 32)
        sum += gr[j] * gate_k[j * NE + warp];
    #pragma unroll
    for (int o = 16; o > 0; o >>= 1)
        sum += __shfl_down_sync(0xFFFFFFFFu, sum, o);
    if (lane == 0) logits[warp] = sum;
    __syncthreads();
    if (threadIdx.x == 0) {
        int b0 = 0; float v0 = logits[0];
        #pragma unroll
        for (int e = 1; e < NE; e++)
            if (logits[e] > v0) { v0 = logits[e]; b0 = e; }
        int b1 = -1; float v1 = -3.0e38f;
        #pragma unroll
        for (int e = 0; e < NE; e++) {
            if (e == b0) continue;
            if (logits[e] > v1) { v1 = logits[e]; b1 = e; }
        }
        g_weights[t * 2 + 0] = 1.f / (1.f + expf(-v0));
        g_weights[t * 2 + 1] = 1.f / (1.f + expf(-v1));
        int s0 = atomicAdd(&g_counts[b0], 1);
        g_slots[b0 * TTOT + s0] = t * 2 + 0;
        int s1 = atomicAdd(&g_counts[b1], 1);
        g_slots[b1 * TTOT + s1] = t * 2 + 1;
    }
}

// transpose + fp32 -> fp16: src [e][K][N] -> dst [e][N][K].
// 64(k) x 32(n) tile; writes are 128B-coalesced half2.
// Destination selected IN DEVICE CODE (ATS host-shadow-pointer hazard).
__global__ __launch_bounds__(256) void tconv_kernel(
    const float* __restrict__ src, int which, int K, int N)
{
    __half* dst;
    if (which == 0)      dst = g_wgT;
    else if (which == 1) dst = g_wuT;
    else                 dst = g_wdT;

    __shared__ float tile[64][33];
    int e = blockIdx.z;
    const float* s = src + (size_t)e * K * N;
    int tx = threadIdx.x & 31, ty = threadIdx.x >> 5;    // (32, 8)
    int n = blockIdx.x * 32 + tx;
    int k = blockIdx.y * 64 + ty;
    #pragma unroll
    for (int i = 0; i < 64; i += 8)
        tile[ty + i][tx] = s[(size_t)(k + i) * N + n];
    __syncthreads();

    int wn = threadIdx.x >> 5;          // 0..7 (n within tile)
    int wk = (threadIdx.x & 31) * 2;    // 0..62 (k pair)
    size_t base = (size_t)e * N * K;
    int k2 = blockIdx.y * 64 + wk;
    #pragma unroll
    for (int p = 0; p < 32; p += 8) {
        int n2 = blockIdx.x * 32 + wn + p;
        __half2 h = __floats2half2_rn(tile[wk][wn + p], tile[wk + 1][wn + p]);
        *(__half2*)&dst[base + (size_t)n2 * K + k2] = h;
    }
}

// gather x rows per expert slot -> fp16, zero the 128-padding rows
__global__ __launch_bounds__(256) void gather_x_kernel(const float* __restrict__ x)
{
    int gid = blockIdx.x;
    int e = gid >> 11;
    int s = gid & (TTOT - 1);
    int count = g_counts[e];
    int padded = (count + 127) & ~127;
    if (s >= padded) return;
    size_t dst = (size_t)(e * TTOT + s) * EMBED;
    if (s < count) {
        int token = g_slots[e * TTOT + s] >> 1;
        const float* xr = x + (size_t)token * EMBED;
        for (int j = threadIdx.x; j < EMBED; j += 256)
            g_x16[dst + j] = __float2half_rn(xr[j]);
    } else {
        __half z = __float2half(0.f);
        for (int j = threadIdx.x; j < EMBED; j += 256)
            g_x16[dst + j] = z;
    }
}

// ===================== gate/up MMA kernel (mma.sync fp16 + ldmatrix) ========
// CTA: M=128 slots x N=64 cols of HID for BOTH gate and up.
// 8 warps as 2(m) x 4(n). K chunks of 64, cp.async double-buffered, occ 2.
extern __shared__ __half dynsm[];

__global__ __launch_bounds__(256, 2) void gateup_mma_kernel()
{
    int e = blockIdx.z;
    int count = g_counts[e];
    int padded = (count + 127) & ~127;
    int rowBase = blockIdx.y * 128;
    if (rowBase >= padded) return;
    int n0 = blockIdx.x * 64;

    int tid = threadIdx.x, wid = tid >> 5, lane = tid & 31;
    int qr = lane >> 2, qc = lane & 3;
    int warpM = (wid >> 2) * 64;
    int warpN = (wid & 3) * 16;

    uint32_t sb = smem_u32(dynsm);
    // stage layout (fp16 elem offsets): A 128x72, G 64x72, U 64x72
    const int O_A = 0, O_G = 9216, O_U = 13824;

    int rowA = warpM + (lane & 7) + ((lane >> 3) & 1) * 8;
    int kgA  = ((lane >> 4) & 1) * 8;
    uint32_t aoff = (uint32_t)(rowA * KS + kgA) * 2;
    int rowB = warpN + ((lane >> 4) & 1) * 8 + (lane & 7);
    int kgB  = ((lane >> 3) & 1) * 8;
    uint32_t boff = (uint32_t)(rowB * KS + kgB) * 2;

    const __half* ax = g_x16 + (size_t)(e * TTOT + rowBase) * EMBED;
    const __half* bg = g_wgT + (size_t)(e * HID + n0) * EMBED;
    const __half* bu = g_wuT + (size_t)(e * HID + n0) * EMBED;

    float accg[4][2][4] = {}, accu[4][2][4] = {};

    const int NCH = EMBED / 64;      // 16
    {   // prefetch chunk 0 into stage 0
        cp_tile(sb + O_A * 2, ax, 128, EMBED, tid);
        cp_tile(sb + O_G * 2, bg, 64, EMBED, tid);
        cp_tile(sb + O_U * 2, bu, 64, EMBED, tid);
        CP_COMMIT();
    }

    for (int c = 0; c < NCH; c++) {
        if (c + 1 < NCH) {
            uint32_t st = sb + ((c + 1) & 1) * (STAGE_E * 2);
            int k0 = (c + 1) * 64;
            cp_tile(st + O_A * 2, ax + k0, 128, EMBED, tid);
            cp_tile(st + O_G * 2, bg + k0, 64, EMBED, tid);
            cp_tile(st + O_U * 2, bu + k0, 64, EMBED, tid);
            CP_COMMIT();
            CP_WAIT1();
        } else {
            CP_WAIT0();
        }
        __syncthreads();

        uint32_t sbase = sb + (c & 1) * (STAGE_E * 2);
        uint32_t aA = sbase + O_A * 2 + aoff;
        uint32_t aG = sbase + O_G * 2 + boff;
        uint32_t aU = sbase + O_U * 2 + boff;

        #pragma unroll
        for (int ks = 0; ks < 4; ks++) {
            uint32_t kb = ks * 32;               // 16 elems = 32 B per k-step
            uint32_t a4[4][4];
            #pragma unroll
            for (int mt = 0; mt < 4; mt++)
                LDSM_X4(a4[mt], aA + mt * (16 * KS * 2) + kb);
            uint32_t g4[4], u4[4];
            LDSM_X4(g4, aG + kb);
            LDSM_X4(u4, aU + kb);

            #pragma unroll
            for (int mt = 0; mt < 4; mt++)
                #pragma unroll
                for (int nt = 0; nt < 2; nt++) {
                    mma16816(accg[mt][nt], a4[mt], &g4[nt * 2]);
                    mma16816(accu[mt][nt], a4[mt], &u4[nt * 2]);
                }
        }
        __syncthreads();
    }

    // epilogue: act = gelu(gate) * up -> fp16
    size_t slot = (size_t)e * TTOT + rowBase;
    #pragma unroll
    for (int mt = 0; mt < 4; mt++)
        #pragma unroll
        for (int nt = 0; nt < 2; nt++) {
            int r0 = warpM + mt * 16 + qr;
            int col = n0 + warpN + nt * 8 + qc * 2;
            float v00 = gelu_tanh(accg[mt][nt][0]) * accu[mt][nt][0];
            float v01 = gelu_tanh(accg[mt][nt][1]) * accu[mt][nt][1];
            float v10 = gelu_tanh(accg[mt][nt][2]) * accu[mt][nt][2];
            float v11 = gelu_tanh(accg[mt][nt][3]) * accu[mt][nt][3];
            *(uint32_t*)&g_act[(slot + r0) * HID + col]     = pack2h(v00, v01);
            *(uint32_t*)&g_act[(slot + r0 + 8) * HID + col] = pack2h(v10, v11);
        }
}

// ===================== down MMA kernel ======================================
// CTA: M=128 slots x N=128 cols of EMBED. warps 2x4 -> warp 64x32, occ 2.
__global__ __launch_bounds__(256, 2) void down_mma_kernel(const float* __restrict__ scale)
{
    int e = blockIdx.z;
    int count = g_counts[e];
    int padded = (count + 127) & ~127;
    int rowBase = blockIdx.y * 128;
    if (rowBase >= padded) return;
    int n0 = blockIdx.x * 128;

    int tid = threadIdx.x, wid = tid >> 5, lane = tid & 31;
    int qr = lane >> 2, qc = lane & 3;
    int warpM = (wid >> 2) * 64;
    int warpN = (wid & 3) * 32;

    uint32_t sb = smem_u32(dynsm);
    const int O_A = 0, O_B = 9216;   // A 128x72, B 128x72

    int rowA = warpM + (lane & 7) + ((lane >> 3) & 1) * 8;
    int kgA  = ((lane >> 4) & 1) * 8;
    uint32_t aoff = (uint32_t)(rowA * KS + kgA) * 2;
    int rowB = warpN + ((lane >> 4) & 1) * 8 + (lane & 7);
    int kgB  = ((lane >> 3) & 1) * 8;
    uint32_t boff = (uint32_t)(rowB * KS + kgB) * 2;

    const __half* aa = g_act + (size_t)(e * TTOT + rowBase) * HID;
    const __half* bb = g_wdT + (size_t)(e * EMBED + n0) * HID;

    float acc[4][4][4] = {};

    const int NCH = HID / 64;       // 32
    {
        cp_tile(sb + O_A * 2, aa, 128, HID, tid);
        cp_tile(sb + O_B * 2, bb, 128, HID, tid);
        CP_COMMIT();
    }

    for (int c = 0; c < NCH; c++) {
        if (c + 1 < NCH) {
            uint32_t st = sb + ((c + 1) & 1) * (STAGE_E * 2);
            int k0 = (c + 1) * 64;
            cp_tile(st + O_A * 2, aa + k0, 128, HID, tid);
            cp_tile(st + O_B * 2, bb + k0, 128, HID, tid);
            CP_COMMIT();
            CP_WAIT1();
        } else {
            CP_WAIT0();
        }
        __syncthreads();

        uint32_t sbase = sb + (c & 1) * (STAGE_E * 2);
        uint32_t aA = sbase + O_A * 2 + aoff;
        uint32_t aB = sbase + O_B * 2 + boff;

        #pragma unroll
        for (int ks = 0; ks < 4; ks++) {
            uint32_t kb = ks * 32;
            uint32_t a4[4][4];
            #pragma unroll
            for (int mt = 0; mt < 4; mt++)
                LDSM_X4(a4[mt], aA + mt * (16 * KS * 2) + kb);
            uint32_t b8[8];
            LDSM_X4(b8,     aB + kb);
            LDSM_X4(b8 + 4, aB + (16 * KS * 2) + kb);

            #pragma unroll
            for (int mt = 0; mt < 4; mt++)
                #pragma unroll
                for (int nt = 0; nt < 4; nt++)
                    mma16816(acc[mt][nt], a4[mt], &b8[nt * 2]);
        }
        __syncthreads();
    }

    float sc = scale[e];
    #pragma unroll
    for (int mt = 0; mt < 4; mt++) {
        int r0 = warpM + mt * 16 + qr;
        int s0 = rowBase + r0, s1 = rowBase + r0 + 8;
        int p0 = (s0 < count) ? g_slots[e * TTOT + s0] : -1;
        int p1 = (s1 < count) ? g_slots[e * TTOT + s1] : -1;
        #pragma unroll
        for (int nt = 0; nt < 4; nt++) {
            int col = n0 + warpN + nt * 8 + qc * 2;
            if (p0 >= 0) {
                float2 v = make_float2(acc[mt][nt][0] * sc, acc[mt][nt][1] * sc);
                *(float2*)&g_tmp[(size_t)p0 * EMBED + col] = v;
            }
            if (p1 >= 0) {
                float2 v = make_float2(acc[mt][nt][2] * sc, acc[mt][nt][3] * sc);
                *(float2*)&g_tmp[(size_t)p1 * EMBED + col] = v;
            }
        }
    }
}

// ===================== combine ==============================================
__global__ __launch_bounds__(256) void combine_kernel(float* __restrict__ out)
{
    int i = blockIdx.x * blockDim.x + threadIdx.x;
    int t = i >> 10;
    int n = i & 1023;
    float w0 = g_weights[t * 2 + 0];
    float w1 = g_weights[t * 2 + 1];
    out[i] = w0 * g_tmp[(size_t)(t * 2 + 0) * EMBED + n]
           + w1 * g_tmp[(size_t)(t * 2 + 1) * EMBED + n];
}

// ===================== host launcher ========================================
extern "C" void kernel_launch(void* const* d_in, const int* in_sizes, int n_in,
                              void* d_out, int out_size)
{
    const float* x     = (const float*)d_in[0];
    const float* gi    = (const float*)d_in[1];
    const float* gk    = (const float*)d_in[2];
    const float* scale = (const float*)d_in[3];
    const float* wg    = (const float*)d_in[4];
    const float* wu    = (const float*)d_in[5];
    const float* wd    = (const float*)d_in[6];
    float* out = (float*)d_out;

    cudaFuncSetAttribute(gateup_mma_kernel,
                         cudaFuncAttributeMaxDynamicSharedMemorySize, SMEM_BYTES);
    cudaFuncSetAttribute(down_mma_kernel,
                         cudaFuncAttributeMaxDynamicSharedMemorySize, SMEM_BYTES);

    zero_counts_kernel<<<1, 32>>>();
    route_kernel<<<TTOT, 256>>>(gi, gk);
    gather_x_kernel<<<NE * TTOT, 256>>>(x);
    tconv_kernel<<<dim3(HID / 32, EMBED / 64, NE), 256>>>(wg, 0, EMBED, HID);
    tconv_kernel<<<dim3(HID / 32, EMBED / 64, NE), 256>>>(wu, 1, EMBED, HID);
    tconv_kernel<<<dim3(EMBED / 32, HID / 64, NE), 256>>>(wd, 2, HID, EMBED);

    gateup_mma_kernel<<<dim3(HID / 64, TTOT / 128, NE), 256, SMEM_BYTES>>>();
    down_mma_kernel<<<dim3(EMBED / 128, TTOT / 128, NE), 256, SMEM_BYTES>>>(scale);
    combine_kernel<<<(TTOT * EMBED) / 256, 256>>>(out);
}

// round 13
// speedup vs baseline: 5.0701x; 1.0181x over previous
#include <cuda_runtime.h>
#include <cuda_fp16.h>
#include <math.h>
#include <stdint.h>

// Problem constants (B=2, T=1024)
#define TTOT   2048
#define EMBED  1024
#define HID    2048
#define NE     8

// K-chunk = 64 fp16. smem row = 64 data + 8 pad = 72 elems (144B).
#define KS 72
#define STAGE_E 18432                 // elems per stage (both kernels) = 36864 B
#define SMEM_BYTES (3 * STAGE_E * 2)  // 110592 B triple-buffered

// ===================== scratch ==============================================
__device__ __align__(16) int   g_counts[NE];
__device__ __align__(16) int   g_slots[NE * TTOT];
__device__ __align__(16) float g_weights[TTOT * 2];
__device__ __align__(16) float g_tmp[(size_t)TTOT * 2 * EMBED];

__device__ __align__(16) __half g_x16[(size_t)NE * TTOT * EMBED];
__device__ __align__(16) __half g_wgT[(size_t)NE * HID * EMBED];
__device__ __align__(16) __half g_wuT[(size_t)NE * HID * EMBED];
__device__ __align__(16) __half g_wdT[(size_t)NE * EMBED * HID];
__device__ __align__(16) __half g_act[(size_t)NE * TTOT * HID];

// ===================== helpers ==============================================
__device__ __forceinline__ uint32_t smem_u32(const void* p) {
    uint32_t a;
    asm("{ .reg .u64 t; cvta.to.shared.u64 t, %1; cvt.u32.u64 %0, t; }"
        : "=r"(a) : "l"(p));
    return a;
}
#define CP16(dst, src) \
    asm volatile("cp.async.cg.shared.global [%0], [%1], 16;" :: "r"(dst), "l"(src))
#define CP_COMMIT() asm volatile("cp.async.commit_group;" ::: "memory")
#define CP_WAIT2()  asm volatile("cp.async.wait_group 2;" ::: "memory")
#define CP_WAIT1()  asm volatile("cp.async.wait_group 1;" ::: "memory")
#define CP_WAIT0()  asm volatile("cp.async.wait_group 0;" ::: "memory")

#define LDSM_X4(r, addr) \
    asm volatile("ldmatrix.sync.aligned.m8n8.x4.shared.b16 {%0,%1,%2,%3}, [%4];" \
        : "=r"((r)[0]), "=r"((r)[1]), "=r"((r)[2]), "=r"((r)[3]) : "r"(addr))

__device__ __forceinline__ void mma16816(float* d, const uint32_t* a, const uint32_t* b)
{
    asm volatile(
        "mma.sync.aligned.m16n8k16.row.col.f32.f16.f16.f32 "
        "{%0,%1,%2,%3}, {%4,%5,%6,%7}, {%8,%9}, {%0,%1,%2,%3};"
        : "+f"(d[0]), "+f"(d[1]), "+f"(d[2]), "+f"(d[3])
        : "r"(a[0]), "r"(a[1]), "r"(a[2]), "r"(a[3]), "r"(b[0]), "r"(b[1]));
}

__device__ __forceinline__ uint32_t pack2h(float x, float y) {
    __half2 h = __floats2half2_rn(x, y);
    return *reinterpret_cast<uint32_t*>(&h);
}

__device__ __forceinline__ float gelu_tanh(float x) {
    const float c = 0.7978845608028654f;
    float inner = c * (x + 0.044715f * x * x * x);
    return 0.5f * x * (1.f + tanhf(inner));
}

// async gmem -> smem copy of a rows x 64-fp16 tile (smem row stride KS)
__device__ __forceinline__ void cp_tile(uint32_t dst_sb, const __half* src,
                                        int rows, int stride, int tid)
{
    int total = rows * 8;                 // 8 x 16B per row
    for (int o = tid; o < total; o += 256) {
        int r = o >> 3, ch = o & 7;
        uint32_t d = dst_sb + (uint32_t)r * (KS * 2) + ch * 16;
        CP16(d, src + (size_t)r * stride + ch * 8);
    }
}

// ===================== small kernels ========================================
__global__ void zero_counts_kernel() {
    if (threadIdx.x < NE) g_counts[threadIdx.x] = 0;
}

__global__ __launch_bounds__(256) void route_kernel(
    const float* __restrict__ gate_in, const float* __restrict__ gate_k)
{
    int t = blockIdx.x;
    int warp = threadIdx.x >> 5, lane = threadIdx.x & 31;
    __shared__ float logits[NE];
    const float* gr = gate_in + (size_t)t * EMBED;
    float sum = 0.f;
    for (int j = lane; j < EMBED; j += 32)
        sum += gr[j] * gate_k[j * NE + warp];
    #pragma unroll
    for (int o = 16; o > 0; o >>= 1)
        sum += __shfl_down_sync(0xFFFFFFFFu, sum, o);
    if (lane == 0) logits[warp] = sum;
    __syncthreads();
    if (threadIdx.x == 0) {
        int b0 = 0; float v0 = logits[0];
        #pragma unroll
        for (int e = 1; e < NE; e++)
            if (logits[e] > v0) { v0 = logits[e]; b0 = e; }
        int b1 = -1; float v1 = -3.0e38f;
        #pragma unroll
        for (int e = 0; e < NE; e++) {
            if (e == b0) continue;
            if (logits[e] > v1) { v1 = logits[e]; b1 = e; }
        }
        g_weights[t * 2 + 0] = 1.f / (1.f + expf(-v0));
        g_weights[t * 2 + 1] = 1.f / (1.f + expf(-v1));
        int s0 = atomicAdd(&g_counts[b0], 1);
        g_slots[b0 * TTOT + s0] = t * 2 + 0;
        int s1 = atomicAdd(&g_counts[b1], 1);
        g_slots[b1 * TTOT + s1] = t * 2 + 1;
    }
}

// ALL weight transposes in ONE launch: grid (1024, 1, 3*NE).
// src [e][K][N] -> dst [e][N][K] fp16, 64(k)x32(n) tiles, coalesced both ways.
// Destination selected IN DEVICE CODE (ATS host-shadow-pointer hazard).
__global__ __launch_bounds__(256) void tconv_all_kernel(
    const float* __restrict__ wg, const float* __restrict__ wu,
    const float* __restrict__ wd)
{
    int which = blockIdx.z >> 3;
    int e = blockIdx.z & 7;
    const float* src; __half* dst; int K, N;
    if (which == 0)      { src = wg; dst = g_wgT; K = EMBED; N = HID; }
    else if (which == 1) { src = wu; dst = g_wuT; K = EMBED; N = HID; }
    else                 { src = wd; dst = g_wdT; K = HID; N = EMBED; }
    int nb = N >> 5;                       // n-blocks
    int bx = blockIdx.x % nb, by = blockIdx.x / nb;

    __shared__ float tile[64][33];
    const float* s = src + (size_t)e * K * N;
    int tx = threadIdx.x & 31, ty = threadIdx.x >> 5;
    int n = bx * 32 + tx;
    int k = by * 64 + ty;
    #pragma unroll
    for (int i = 0; i < 64; i += 8)
        tile[ty + i][tx] = s[(size_t)(k + i) * N + n];
    __syncthreads();

    int wn = threadIdx.x >> 5;
    int wk = (threadIdx.x & 31) * 2;
    size_t base = (size_t)e * N * K;
    int k2 = by * 64 + wk;
    #pragma unroll
    for (int p = 0; p < 32; p += 8) {
        int n2 = bx * 32 + wn + p;
        __half2 h = __floats2half2_rn(tile[wk][wn + p], tile[wk + 1][wn + p]);
        *(__half2*)&dst[base + (size_t)n2 * K + k2] = h;
    }
}

// gather x rows per expert slot -> fp16, zero the 128-padding rows
__global__ __launch_bounds__(256) void gather_x_kernel(const float* __restrict__ x)
{
    int gid = blockIdx.x;
    int e = gid >> 11;
    int s = gid & (TTOT - 1);
    int count = g_counts[e];
    int padded = (count + 127) & ~127;
    if (s >= padded) return;
    size_t dst = (size_t)(e * TTOT + s) * EMBED;
    if (s < count) {
        int token = g_slots[e * TTOT + s] >> 1;
        const float* xr = x + (size_t)token * EMBED;
        for (int j = threadIdx.x; j < EMBED; j += 256)
            g_x16[dst + j] = __float2half_rn(xr[j]);
    } else {
        __half z = __float2half(0.f);
        for (int j = threadIdx.x; j < EMBED; j += 256)
            g_x16[dst + j] = z;
    }
}

// ===================== gate/up MMA kernel (mma.sync fp16 + ldmatrix) ========
// CTA: M=128 slots x N=64 cols of HID for BOTH gate and up.
// 8 warps as 2(m) x 4(n). K chunks of 64, 3-stage cp.async pipeline, occ 2.
extern __shared__ __half dynsm[];

__global__ __launch_bounds__(256, 2) void gateup_mma_kernel()
{
    int e = blockIdx.z;
    int count = g_counts[e];
    int padded = (count + 127) & ~127;
    int rowBase = blockIdx.y * 128;
    if (rowBase >= padded) return;
    int n0 = blockIdx.x * 64;

    int tid = threadIdx.x, wid = tid >> 5, lane = tid & 31;
    int qr = lane >> 2, qc = lane & 3;
    int warpM = (wid >> 2) * 64;
    int warpN = (wid & 3) * 16;

    uint32_t sb = smem_u32(dynsm);
    const int O_A = 0, O_G = 9216, O_U = 13824;   // fp16 elem offsets in stage

    int rowA = warpM + (lane & 7) + ((lane >> 3) & 1) * 8;
    int kgA  = ((lane >> 4) & 1) * 8;
    uint32_t aoff = (uint32_t)(rowA * KS + kgA) * 2;
    int rowB = warpN + ((lane >> 4) & 1) * 8 + (lane & 7);
    int kgB  = ((lane >> 3) & 1) * 8;
    uint32_t boff = (uint32_t)(rowB * KS + kgB) * 2;

    const __half* ax = g_x16 + (size_t)(e * TTOT + rowBase) * EMBED;
    const __half* bg = g_wgT + (size_t)(e * HID + n0) * EMBED;
    const __half* bu = g_wuT + (size_t)(e * HID + n0) * EMBED;

    float accg[4][2][4] = {}, accu[4][2][4] = {};

    const int NCH = EMBED / 64;      // 16
    // prefetch chunks 0,1 into stages 0,1
    #pragma unroll
    for (int p = 0; p < 2; p++) {
        uint32_t st = sb + p * (STAGE_E * 2);
        int k0 = p * 64;
        cp_tile(st + O_A * 2, ax + k0, 128, EMBED, tid);
        cp_tile(st + O_G * 2, bg + k0, 64, EMBED, tid);
        cp_tile(st + O_U * 2, bu + k0, 64, EMBED, tid);
        CP_COMMIT();
    }

    int stage = 0;
    for (int c = 0; c < NCH; c++) {
        if (c + 2 < NCH) {
            int fs = stage + 2; if (fs >= 3) fs -= 3;
            uint32_t st = sb + fs * (STAGE_E * 2);
            int k0 = (c + 2) * 64;
            cp_tile(st + O_A * 2, ax + k0, 128, EMBED, tid);
            cp_tile(st + O_G * 2, bg + k0, 64, EMBED, tid);
            cp_tile(st + O_U * 2, bu + k0, 64, EMBED, tid);
            CP_COMMIT();
            CP_WAIT2();
        } else if (c + 1 < NCH) {
            CP_WAIT1();
        } else {
            CP_WAIT0();
        }
        __syncthreads();

        uint32_t sbase = sb + stage * (STAGE_E * 2);
        uint32_t aA = sbase + O_A * 2 + aoff;
        uint32_t aG = sbase + O_G * 2 + boff;
        uint32_t aU = sbase + O_U * 2 + boff;

        #pragma unroll
        for (int ks = 0; ks < 4; ks++) {
            uint32_t kb = ks * 32;               // 16 elems = 32 B per k-step
            uint32_t a4[4][4];
            #pragma unroll
            for (int mt = 0; mt < 4; mt++)
                LDSM_X4(a4[mt], aA + mt * (16 * KS * 2) + kb);
            uint32_t g4[4], u4[4];
            LDSM_X4(g4, aG + kb);
            LDSM_X4(u4, aU + kb);

            #pragma unroll
            for (int mt = 0; mt < 4; mt++)
                #pragma unroll
                for (int nt = 0; nt < 2; nt++) {
                    mma16816(accg[mt][nt], a4[mt], &g4[nt * 2]);
                    mma16816(accu[mt][nt], a4[mt], &u4[nt * 2]);
                }
        }
        __syncthreads();
        if (++stage == 3) stage = 0;
    }

    // epilogue: act = gelu(gate) * up -> fp16
    size_t slot = (size_t)e * TTOT + rowBase;
    #pragma unroll
    for (int mt = 0; mt < 4; mt++)
        #pragma unroll
        for (int nt = 0; nt < 2; nt++) {
            int r0 = warpM + mt * 16 + qr;
            int col = n0 + warpN + nt * 8 + qc * 2;
            float v00 = gelu_tanh(accg[mt][nt][0]) * accu[mt][nt][0];
            float v01 = gelu_tanh(accg[mt][nt][1]) * accu[mt][nt][1];
            float v10 = gelu_tanh(accg[mt][nt][2]) * accu[mt][nt][2];
            float v11 = gelu_tanh(accg[mt][nt][3]) * accu[mt][nt][3];
            *(uint32_t*)&g_act[(slot + r0) * HID + col]     = pack2h(v00, v01);
            *(uint32_t*)&g_act[(slot + r0 + 8) * HID + col] = pack2h(v10, v11);
        }
}

// ===================== down MMA kernel ======================================
// CTA: M=128 slots x N=128 cols of EMBED. warps 2x4 -> warp 64x32, occ 2.
__global__ __launch_bounds__(256, 2) void down_mma_kernel(const float* __restrict__ scale)
{
    int e = blockIdx.z;
    int count = g_counts[e];
    int padded = (count + 127) & ~127;
    int rowBase = blockIdx.y * 128;
    if (rowBase >= padded) return;
    int n0 = blockIdx.x * 128;

    int tid = threadIdx.x, wid = tid >> 5, lane = tid & 31;
    int qr = lane >> 2, qc = lane & 3;
    int warpM = (wid >> 2) * 64;
    int warpN = (wid & 3) * 32;

    uint32_t sb = smem_u32(dynsm);
    const int O_A = 0, O_B = 9216;   // A 128x72, B 128x72

    int rowA = warpM + (lane & 7) + ((lane >> 3) & 1) * 8;
    int kgA  = ((lane >> 4) & 1) * 8;
    uint32_t aoff = (uint32_t)(rowA * KS + kgA) * 2;
    int rowB = warpN + ((lane >> 4) & 1) * 8 + (lane & 7);
    int kgB  = ((lane >> 3) & 1) * 8;
    uint32_t boff = (uint32_t)(rowB * KS + kgB) * 2;

    const __half* aa = g_act + (size_t)(e * TTOT + rowBase) * HID;
    const __half* bb = g_wdT + (size_t)(e * EMBED + n0) * HID;

    float acc[4][4][4] = {};

    const int NCH = HID / 64;       // 32
    #pragma unroll
    for (int p = 0; p < 2; p++) {
        uint32_t st = sb + p * (STAGE_E * 2);
        int k0 = p * 64;
        cp_tile(st + O_A * 2, aa + k0, 128, HID, tid);
        cp_tile(st + O_B * 2, bb + k0, 128, HID, tid);
        CP_COMMIT();
    }

    int stage = 0;
    for (int c = 0; c < NCH; c++) {
        if (c + 2 < NCH) {
            int fs = stage + 2; if (fs >= 3) fs -= 3;
            uint32_t st = sb + fs * (STAGE_E * 2);
            int k0 = (c + 2) * 64;
            cp_tile(st + O_A * 2, aa + k0, 128, HID, tid);
            cp_tile(st + O_B * 2, bb + k0, 128, HID, tid);
            CP_COMMIT();
            CP_WAIT2();
        } else if (c + 1 < NCH) {
            CP_WAIT1();
        } else {
            CP_WAIT0();
        }
        __syncthreads();

        uint32_t sbase = sb + stage * (STAGE_E * 2);
        uint32_t aA = sbase + O_A * 2 + aoff;
        uint32_t aB = sbase + O_B * 2 + boff;

        #pragma unroll
        for (int ks = 0; ks < 4; ks++) {
            uint32_t kb = ks * 32;
            uint32_t a4[4][4];
            #pragma unroll
            for (int mt = 0; mt < 4; mt++)
                LDSM_X4(a4[mt], aA + mt * (16 * KS * 2) + kb);
            uint32_t b8[8];
            LDSM_X4(b8,     aB + kb);
            LDSM_X4(b8 + 4, aB + (16 * KS * 2) + kb);

            #pragma unroll
            for (int mt = 0; mt < 4; mt++)
                #pragma unroll
                for (int nt = 0; nt < 4; nt++)
                    mma16816(acc[mt][nt], a4[mt], &b8[nt * 2]);
        }
        __syncthreads();
        if (++stage == 3) stage = 0;
    }

    float sc = scale[e];
    #pragma unroll
    for (int mt = 0; mt < 4; mt++) {
        int r0 = warpM + mt * 16 + qr;
        int s0 = rowBase + r0, s1 = rowBase + r0 + 8;
        int p0 = (s0 < count) ? g_slots[e * TTOT + s0] : -1;
        int p1 = (s1 < count) ? g_slots[e * TTOT + s1] : -1;
        #pragma unroll
        for (int nt = 0; nt < 4; nt++) {
            int col = n0 + warpN + nt * 8 + qc * 2;
            if (p0 >= 0) {
                float2 v = make_float2(acc[mt][nt][0] * sc, acc[mt][nt][1] * sc);
                *(float2*)&g_tmp[(size_t)p0 * EMBED + col] = v;
            }
            if (p1 >= 0) {
                float2 v = make_float2(acc[mt][nt][2] * sc, acc[mt][nt][3] * sc);
                *(float2*)&g_tmp[(size_t)p1 * EMBED + col] = v;
            }
        }
    }
}

// ===================== combine ==============================================
__global__ __launch_bounds__(256) void combine_kernel(float* __restrict__ out)
{
    int i = blockIdx.x * blockDim.x + threadIdx.x;
    int t = i >> 10;
    int n = i & 1023;
    float w0 = g_weights[t * 2 + 0];
    float w1 = g_weights[t * 2 + 1];
    out[i] = w0 * g_tmp[(size_t)(t * 2 + 0) * EMBED + n]
           + w1 * g_tmp[(size_t)(t * 2 + 1) * EMBED + n];
}

// ===================== host launcher ========================================
extern "C" void kernel_launch(void* const* d_in, const int* in_sizes, int n_in,
                              void* d_out, int out_size)
{
    const float* x     = (const float*)d_in[0];
    const float* gi    = (const float*)d_in[1];
    const float* gk    = (const float*)d_in[2];
    const float* scale = (const float*)d_in[3];
    const float* wg    = (const float*)d_in[4];
    const float* wu    = (const float*)d_in[5];
    const float* wd    = (const float*)d_in[6];
    float* out = (float*)d_out;

    cudaFuncSetAttribute(gateup_mma_kernel,
                         cudaFuncAttributeMaxDynamicSharedMemorySize, SMEM_BYTES);
    cudaFuncSetAttribute(down_mma_kernel,
                         cudaFuncAttributeMaxDynamicSharedMemorySize, SMEM_BYTES);

    zero_counts_kernel<<<1, 32>>>();
    route_kernel<<<TTOT, 256>>>(gi, gk);
    gather_x_kernel<<<NE * TTOT, 256>>>(x);
    tconv_all_kernel<<<dim3(1024, 1, 3 * NE), 256>>>(wg, wu, wd);

    gateup_mma_kernel<<<dim3(HID / 64, TTOT / 128, NE), 256, SMEM_BYTES>>>();
    down_mma_kernel<<<dim3(EMBED / 128, TTOT / 128, NE), 256, SMEM_BYTES>>>(scale);
    combine_kernel<<<(TTOT * EMBED) / 256, 256>>>(out);
}